// round 15
// baseline (speedup 1.0000x reference)
#include <cuda_runtime.h>
#include <cuda_bf16.h>
#include <math.h>
#include <stdint.h>

#define NNODES 50000
#define DIMC   128
#define DD     16
#define HH     8
#define HDD    16
#define SLOPEC 0.2f
#define ALPHAC 0.1f
#define LNEPS  1e-5f
// ln(17)/16
#define SCORE_SCALE 0.17707583400351351f

// Scratch: 15*N*128 floats (~384MB)
__device__ float g_scratch[(size_t)NNODES * 1920];

__device__ __forceinline__ void bfsplit(float v0, float v1, uint32_t& hi, uint32_t& lo) {
    __nv_bfloat16 h0 = __float2bfloat16(v0);
    __nv_bfloat16 h1 = __float2bfloat16(v1);
    float r0 = v0 - __bfloat162float(h0);
    float r1 = v1 - __bfloat162float(h1);
    __nv_bfloat16 l0 = __float2bfloat16(r0);
    __nv_bfloat16 l1 = __float2bfloat16(r1);
    hi = ((uint32_t)__bfloat16_as_ushort(h1) << 16) | (uint32_t)__bfloat16_as_ushort(h0);
    lo = ((uint32_t)__bfloat16_as_ushort(l1) << 16) | (uint32_t)__bfloat16_as_ushort(l0);
}

__device__ __forceinline__ void mma16(float* c, const uint32_t* a, const uint32_t* b) {
    asm volatile("mma.sync.aligned.m16n8k16.row.col.f32.bf16.bf16.f32 "
        "{%0,%1,%2,%3}, {%4,%5,%6,%7}, {%8,%9}, {%0,%1,%2,%3};\n"
        : "+f"(c[0]), "+f"(c[1]), "+f"(c[2]), "+f"(c[3])
        : "r"(a[0]), "r"(a[1]), "r"(a[2]), "r"(a[3]), "r"(b[0]), "r"(b[1]));
}

// ---------------------------------------------------------------------------
// LayerNorm (optionally in+add, optionally store the pre-LN sum)
// ---------------------------------------------------------------------------
__global__ void k_ln(const float* __restrict__ in, const float* __restrict__ add,
                     const float* __restrict__ g, const float* __restrict__ b,
                     float* __restrict__ out, float* __restrict__ sum_out, int n)
{
    int row  = blockIdx.x * 8 + (threadIdx.x >> 5);
    int lane = threadIdx.x & 31;
    if (row >= n) return;

    float4 v = ((const float4*)in)[(size_t)row * 32 + lane];
    if (add) {
        float4 w = ((const float4*)add)[(size_t)row * 32 + lane];
        v.x += w.x; v.y += w.y; v.z += w.z; v.w += w.w;
    }
    if (sum_out) ((float4*)sum_out)[(size_t)row * 32 + lane] = v;

    float s = v.x + v.y + v.z + v.w;
    #pragma unroll
    for (int o = 16; o; o >>= 1) s += __shfl_xor_sync(0xffffffffu, s, o);
    float mu = s * (1.0f / 128.0f);

    float dx = v.x - mu, dy = v.y - mu, dz = v.z - mu, dw = v.w - mu;
    float vs = dx * dx + dy * dy + dz * dz + dw * dw;
    #pragma unroll
    for (int o = 16; o; o >>= 1) vs += __shfl_xor_sync(0xffffffffu, vs, o);
    float rs = rsqrtf(vs * (1.0f / 128.0f) + LNEPS);

    float4 gg = ((const float4*)g)[lane];
    float4 bb = ((const float4*)b)[lane];
    float4 o4;
    o4.x = dx * rs * gg.x + bb.x;
    o4.y = dy * rs * gg.y + bb.y;
    o4.z = dz * rs * gg.z + bb.z;
    o4.w = dw * rs * gg.w + bb.w;
    ((float4*)out)[(size_t)row * 32 + lane] = o4;
}

// ---------------------------------------------------------------------------
// Projection GEMM: R10-proven bf16x3 (m16n8k16), A+B fp32 split in-kernel.
// Block 128x128, BK=32, double-buffered, 8 warps (4x2), 2 CTAs/SM.
// ---------------------------------------------------------------------------
#define BK      32
#define A_STR2  20
#define B_STR2  136
#define STG_U32 (2*128*A_STR2 + 2*(BK/2)*B_STR2)
#define GEMM_SMEM_BYTES (2*STG_U32*4)

__global__ void __launch_bounds__(256, 2)
k_gemm_tc(const float* __restrict__ A,
          const float* __restrict__ B0, const float* __restrict__ B1,
          const float* __restrict__ B2,
          float* __restrict__ C, float* __restrict__ C2,
          int M, int K, int bNc, int cNc)
{
    extern __shared__ uint32_t smu[];

    int tid  = threadIdx.x;
    int warp = tid >> 5;
    int lane = tid & 31;
    int g    = lane >> 2;
    int tq   = lane & 3;
    int wr   = (warp >> 1) * 32;
    int wc   = (warp & 1) * 64;

    int row0 = blockIdx.y * 128;
    int c0   = blockIdx.x * 128;
    int bi   = c0 / bNc;
    const float* B = (bi == 0) ? B0 : ((bi == 1) ? B1 : B2);
    int bc0  = c0 - bi * bNc;

    int ar = tid >> 3;
    int ak = (tid & 7) << 2;

    float acc[2][8][4] = {};
    float4 pa[4];
    float4 pb0[2], pb1[2];

    int nch = K >> 5;

    #pragma unroll
    for (int s = 0; s < 4; ++s) {
        int node = row0 + ar + s * 32;
        pa[s] = (node < M) ? *(const float4*)&A[(size_t)node * K + ak]
                           : make_float4(0.f, 0.f, 0.f, 0.f);
    }
    #pragma unroll
    for (int s = 0; s < 2; ++s) {
        int slot = tid + s * 256;
        int kp = slot >> 5;
        int cc = (slot & 31) << 2;
        pb0[s] = *(const float4*)&B[(size_t)(2 * kp)     * bNc + bc0 + cc];
        pb1[s] = *(const float4*)&B[(size_t)(2 * kp + 1) * bNc + bc0 + cc];
    }
    {
        uint32_t* AsHi = smu;
        uint32_t* AsLo = AsHi + 128 * A_STR2;
        uint32_t* BsHi = AsLo + 128 * A_STR2;
        uint32_t* BsLo = BsHi + (BK/2) * B_STR2;
        #pragma unroll
        for (int s = 0; s < 4; ++s) {
            int r = ar + s * 32;
            uint32_t h0, l0, h1, l1;
            bfsplit(pa[s].x, pa[s].y, h0, l0);
            bfsplit(pa[s].z, pa[s].w, h1, l1);
            *(uint2*)&AsHi[r * A_STR2 + (ak >> 1)] = make_uint2(h0, h1);
            *(uint2*)&AsLo[r * A_STR2 + (ak >> 1)] = make_uint2(l0, l1);
        }
        #pragma unroll
        for (int s = 0; s < 2; ++s) {
            int slot = tid + s * 256;
            int kp = slot >> 5;
            int cc = (slot & 31) << 2;
            uint32_t h[4], l[4];
            bfsplit(pb0[s].x, pb1[s].x, h[0], l[0]);
            bfsplit(pb0[s].y, pb1[s].y, h[1], l[1]);
            bfsplit(pb0[s].z, pb1[s].z, h[2], l[2]);
            bfsplit(pb0[s].w, pb1[s].w, h[3], l[3]);
            *(uint4*)&BsHi[kp * B_STR2 + cc] = make_uint4(h[0], h[1], h[2], h[3]);
            *(uint4*)&BsLo[kp * B_STR2 + cc] = make_uint4(l[0], l[1], l[2], l[3]);
        }
    }
    __syncthreads();

    for (int ch = 0; ch < nch; ++ch) {
        int cur = ch & 1;
        uint32_t* AsHi = smu + cur * STG_U32;
        uint32_t* AsLo = AsHi + 128 * A_STR2;
        uint32_t* BsHi = AsLo + 128 * A_STR2;
        uint32_t* BsLo = BsHi + (BK/2) * B_STR2;

        bool more = (ch + 1) < nch;
        if (more) {
            int k0 = (ch + 1) << 5;
            #pragma unroll
            for (int s = 0; s < 4; ++s) {
                int node = row0 + ar + s * 32;
                pa[s] = (node < M) ? *(const float4*)&A[(size_t)node * K + k0 + ak]
                                   : make_float4(0.f, 0.f, 0.f, 0.f);
            }
            #pragma unroll
            for (int s = 0; s < 2; ++s) {
                int slot = tid + s * 256;
                int kp = slot >> 5;
                int cc = (slot & 31) << 2;
                pb0[s] = *(const float4*)&B[(size_t)(k0 + 2 * kp)     * bNc + bc0 + cc];
                pb1[s] = *(const float4*)&B[(size_t)(k0 + 2 * kp + 1) * bNc + bc0 + cc];
            }
        }

        #pragma unroll
        for (int ks = 0; ks < 2; ++ks) {
            int kb = ks * 8;
            uint32_t ahi[2][4], alo[2][4];
            #pragma unroll
            for (int mf = 0; mf < 2; ++mf) {
                int r = wr + mf * 16 + g;
                ahi[mf][0] = AsHi[r * A_STR2 + kb + tq];
                ahi[mf][1] = AsHi[(r + 8) * A_STR2 + kb + tq];
                ahi[mf][2] = AsHi[r * A_STR2 + kb + tq + 4];
                ahi[mf][3] = AsHi[(r + 8) * A_STR2 + kb + tq + 4];
                alo[mf][0] = AsLo[r * A_STR2 + kb + tq];
                alo[mf][1] = AsLo[(r + 8) * A_STR2 + kb + tq];
                alo[mf][2] = AsLo[r * A_STR2 + kb + tq + 4];
                alo[mf][3] = AsLo[(r + 8) * A_STR2 + kb + tq + 4];
            }
            #pragma unroll
            for (int nf = 0; nf < 8; ++nf) {
                int c = wc + nf * 8 + g;
                uint32_t bhi[2], blo[2];
                bhi[0] = BsHi[(kb + tq) * B_STR2 + c];
                bhi[1] = BsHi[(kb + tq + 4) * B_STR2 + c];
                blo[0] = BsLo[(kb + tq) * B_STR2 + c];
                blo[1] = BsLo[(kb + tq + 4) * B_STR2 + c];
                #pragma unroll
                for (int mf = 0; mf < 2; ++mf) {
                    mma16(acc[mf][nf], ahi[mf], bhi);
                    mma16(acc[mf][nf], ahi[mf], blo);
                    mma16(acc[mf][nf], alo[mf], bhi);
                }
            }
        }

        if (more) {
            uint32_t* nAsHi = smu + (cur ^ 1) * STG_U32;
            uint32_t* nAsLo = nAsHi + 128 * A_STR2;
            uint32_t* nBsHi = nAsLo + 128 * A_STR2;
            uint32_t* nBsLo = nBsHi + (BK/2) * B_STR2;
            #pragma unroll
            for (int s = 0; s < 4; ++s) {
                int r = ar + s * 32;
                uint32_t h0, l0, h1, l1;
                bfsplit(pa[s].x, pa[s].y, h0, l0);
                bfsplit(pa[s].z, pa[s].w, h1, l1);
                *(uint2*)&nAsHi[r * A_STR2 + (ak >> 1)] = make_uint2(h0, h1);
                *(uint2*)&nAsLo[r * A_STR2 + (ak >> 1)] = make_uint2(l0, l1);
            }
            #pragma unroll
            for (int s = 0; s < 2; ++s) {
                int slot = tid + s * 256;
                int kp = slot >> 5;
                int cc = (slot & 31) << 2;
                uint32_t h[4], l[4];
                bfsplit(pb0[s].x, pb1[s].x, h[0], l[0]);
                bfsplit(pb0[s].y, pb1[s].y, h[1], l[1]);
                bfsplit(pb0[s].z, pb1[s].z, h[2], l[2]);
                bfsplit(pb0[s].w, pb1[s].w, h[3], l[3]);
                *(uint4*)&nBsHi[kp * B_STR2 + cc] = make_uint4(h[0], h[1], h[2], h[3]);
                *(uint4*)&nBsLo[kp * B_STR2 + cc] = make_uint4(l[0], l[1], l[2], l[3]);
            }
            __syncthreads();
        }
    }

    float* Co = C;
    int ostr  = cNc;
    int ocol0 = c0;
    if (C2 && bi == 2) { Co = C2; ostr = 128; ocol0 = bc0; }

    #pragma unroll
    for (int mf = 0; mf < 2; ++mf) {
        #pragma unroll
        for (int nf = 0; nf < 8; ++nf) {
            int col = ocol0 + wc + nf * 8 + 2 * tq;
            #pragma unroll
            for (int half = 0; half < 2; ++half) {
                int row = row0 + wr + mf * 16 + g + half * 8;
                if (row >= M) continue;
                float2 r;
                r.x = acc[mf][nf][half * 2 + 0];
                r.y = acc[mf][nf][half * 2 + 1];
                *(float2*)&Co[(size_t)row * ostr + col] = r;
            }
        }
    }
}

// ---------------------------------------------------------------------------
// Fused FFN v3: 512 threads (16 warps, 4x4), register-prefetched W chunks.
// out = relu(y @ W1 + b1) @ W2 + b2 + rst; hidden never hits DRAM.
// W2(cc) LDGs fly during MMA1; W1(cc+1) LDGs fly during MMA2.
// smem: Y(69.6K) + W(69.6K) + H(69.6K) = 204KB, 1 CTA/SM.
// ---------------------------------------------------------------------------
#define YA_STR 68
#define WB_STR 136
#define Y_PL   (128 * YA_STR)     // u32 per plane
#define W_PL   (64 * WB_STR)
#define FFN_SMEM_BYTES ((2*Y_PL + 2*W_PL + 2*Y_PL) * 4)

__device__ __forceinline__ void ffn_mma_block(const uint32_t* AH, const uint32_t* AL,
                                              const uint32_t* BH, const uint32_t* BL,
                                              float acc[2][4][4],
                                              int wr, int wc, int g, int tq)
{
    #pragma unroll
    for (int ks = 0; ks < 8; ++ks) {
        int kb = ks * 8;
        uint32_t ahi[2][4], alo[2][4];
        #pragma unroll
        for (int mf = 0; mf < 2; ++mf) {
            int r = wr + mf * 16 + g;
            ahi[mf][0] = AH[r * YA_STR + kb + tq];
            ahi[mf][1] = AH[(r + 8) * YA_STR + kb + tq];
            ahi[mf][2] = AH[r * YA_STR + kb + tq + 4];
            ahi[mf][3] = AH[(r + 8) * YA_STR + kb + tq + 4];
            alo[mf][0] = AL[r * YA_STR + kb + tq];
            alo[mf][1] = AL[(r + 8) * YA_STR + kb + tq];
            alo[mf][2] = AL[r * YA_STR + kb + tq + 4];
            alo[mf][3] = AL[(r + 8) * YA_STR + kb + tq + 4];
        }
        #pragma unroll
        for (int nf = 0; nf < 4; ++nf) {
            int c = wc + nf * 8 + g;
            uint32_t bhi[2], blo[2];
            bhi[0] = BH[(kb + tq) * WB_STR + c];
            bhi[1] = BH[(kb + tq + 4) * WB_STR + c];
            blo[0] = BL[(kb + tq) * WB_STR + c];
            blo[1] = BL[(kb + tq + 4) * WB_STR + c];
            #pragma unroll
            for (int mf = 0; mf < 2; ++mf) {
                mma16(acc[mf][nf], ahi[mf], bhi);
                mma16(acc[mf][nf], ahi[mf], blo);
                mma16(acc[mf][nf], alo[mf], bhi);
            }
        }
    }
}

// issue the 8 LDG.128 for one W chunk into registers
__device__ __forceinline__ void ffn_ldg_w(const float* __restrict__ W, int ldw,
                                          int row_off, int col_off, int tid,
                                          float4 pa[4], float4 pb[4])
{
    #pragma unroll
    for (int s = 0; s < 4; ++s) {
        int slot = tid + s * 512;
        int kp = slot >> 5;
        int c4 = (slot & 31) << 2;
        pa[s] = *(const float4*)&W[(size_t)(row_off + 2 * kp)     * ldw + col_off + c4];
        pb[s] = *(const float4*)&W[(size_t)(row_off + 2 * kp + 1) * ldw + col_off + c4];
    }
}

// split prefetched regs and store into W planes
__device__ __forceinline__ void ffn_sts_w(const float4 pa[4], const float4 pb[4],
                                          uint32_t* BH, uint32_t* BL, int tid)
{
    #pragma unroll
    for (int s = 0; s < 4; ++s) {
        int slot = tid + s * 512;
        int kp = slot >> 5;
        int c4 = (slot & 31) << 2;
        uint32_t h[4], l[4];
        bfsplit(pa[s].x, pb[s].x, h[0], l[0]);
        bfsplit(pa[s].y, pb[s].y, h[1], l[1]);
        bfsplit(pa[s].z, pb[s].z, h[2], l[2]);
        bfsplit(pa[s].w, pb[s].w, h[3], l[3]);
        *(uint4*)&BH[kp * WB_STR + c4] = make_uint4(h[0], h[1], h[2], h[3]);
        *(uint4*)&BL[kp * WB_STR + c4] = make_uint4(l[0], l[1], l[2], l[3]);
    }
}

__global__ void __launch_bounds__(512, 1)
k_ffn(const float* __restrict__ Yg, const float* __restrict__ W1,
      const float* __restrict__ b1, const float* __restrict__ W2,
      const float* __restrict__ b2, const float* __restrict__ rst,
      float* __restrict__ out, int M)
{
    extern __shared__ uint32_t smu[];
    uint32_t* YH = smu;
    uint32_t* YL = YH + Y_PL;
    uint32_t* WH = YL + Y_PL;
    uint32_t* WL = WH + W_PL;
    uint32_t* HH2 = WL + W_PL;
    uint32_t* HL2 = HH2 + Y_PL;

    int tid  = threadIdx.x;
    int warp = tid >> 5;
    int lane = tid & 31;
    int g    = lane >> 2;
    int tq   = lane & 3;
    int wr   = (warp >> 2) * 32;   // 0/32/64/96
    int wc   = (warp & 3) * 32;    // 0/32/64/96
    int row0 = blockIdx.x * 128;

    // ---- prefetch W1 chunk 0 while filling Y planes ----
    float4 pwa[4], pwb[4];
    ffn_ldg_w(W1, 512, 0, 0, tid, pwa, pwb);

    // ---- load y rows -> Y planes (once) ----
    #pragma unroll
    for (int s = 0; s < 4; ++s) {
        int slot = tid + s * 512;          // 0..2047
        int r = slot >> 4;                 // 0..127
        int i = slot & 15;                 // 8-float segment 0..15
        int node = row0 + r;
        float4 v  = make_float4(0.f, 0.f, 0.f, 0.f);
        float4 v2 = make_float4(0.f, 0.f, 0.f, 0.f);
        if (node < M) {
            v  = *(const float4*)&Yg[(size_t)node * DIMC + i * 8];
            v2 = *(const float4*)&Yg[(size_t)node * DIMC + i * 8 + 4];
        }
        uint32_t h0, l0, h1, l1, h2, l2, h3, l3;
        bfsplit(v.x,  v.y,  h0, l0);
        bfsplit(v.z,  v.w,  h1, l1);
        bfsplit(v2.x, v2.y, h2, l2);
        bfsplit(v2.z, v2.w, h3, l3);
        *(uint4*)&YH[r * YA_STR + i * 4] = make_uint4(h0, h1, h2, h3);
        *(uint4*)&YL[r * YA_STR + i * 4] = make_uint4(l0, l1, l2, l3);
    }

    float accO[2][4][4] = {};

    #pragma unroll 1
    for (int cc = 0; cc < 4; ++cc) {
        int hc0 = cc * 128;

        // commit W1 chunk to planes
        ffn_sts_w(pwa, pwb, WH, WL, tid);
        __syncthreads();

        // prefetch W2 chunk (flies during MMA1)
        ffn_ldg_w(W2, 128, hc0, 0, tid, pwa, pwb);

        // MMA1: H = y @ W1chunk
        float accH[2][4][4] = {};
        ffn_mma_block(YH, YL, WH, WL, accH, wr, wc, g, tq);
        __syncthreads();          // all reads of WH/WL done

        // H epilogue: relu + bias -> H planes
        #pragma unroll
        for (int mf = 0; mf < 2; ++mf) {
            #pragma unroll
            for (int nf = 0; nf < 4; ++nf) {
                int col = wc + nf * 8 + 2 * tq;
                float bx = b1[hc0 + col];
                float by = b1[hc0 + col + 1];
                #pragma unroll
                for (int half = 0; half < 2; ++half) {
                    int row = wr + mf * 16 + g + half * 8;
                    float rx = fmaxf(accH[mf][nf][half * 2 + 0] + bx, 0.f);
                    float ry = fmaxf(accH[mf][nf][half * 2 + 1] + by, 0.f);
                    uint32_t hh, ll;
                    bfsplit(rx, ry, hh, ll);
                    HH2[row * YA_STR + (col >> 1)] = hh;
                    HL2[row * YA_STR + (col >> 1)] = ll;
                }
            }
        }

        // commit W2 chunk to planes
        ffn_sts_w(pwa, pwb, WH, WL, tid);
        __syncthreads();          // H planes + W2 visible to all

        // prefetch next W1 chunk (flies during MMA2)
        bool more = (cc + 1) < 4;
        if (more) ffn_ldg_w(W1, 512, 0, hc0 + 128, tid, pwa, pwb);

        // MMA2: out += H @ W2chunk
        ffn_mma_block(HH2, HL2, WH, WL, accO, wr, wc, g, tq);
        __syncthreads();          // before next chunk overwrites WH/H planes
    }

    // ---- final epilogue: out = accO + b2 + rst ----
    #pragma unroll
    for (int mf = 0; mf < 2; ++mf) {
        #pragma unroll
        for (int nf = 0; nf < 4; ++nf) {
            int col = wc + nf * 8 + 2 * tq;
            float bx = b2[col];
            float by = b2[col + 1];
            #pragma unroll
            for (int half = 0; half < 2; ++half) {
                int row = row0 + wr + mf * 16 + g + half * 8;
                if (row >= M) continue;
                size_t base = (size_t)row * DIMC + col;
                float2 av = *(const float2*)&rst[base];
                float2 r;
                r.x = accO[mf][nf][half * 2 + 0] + bx + av.x;
                r.y = accO[mf][nf][half * 2 + 1] + by + av.y;
                *(float2*)&out[base] = r;
            }
        }
    }
}

// ---------------------------------------------------------------------------
// Attention v3 (R10): one WARP per node. Emits SoA lists wl[16] fp32 /
// sl[16] u16 per (node, head) + cnt.
// ---------------------------------------------------------------------------
#define FST 256

__global__ void k_attn(const float* __restrict__ fht, const float* __restrict__ attn,
                       const int* __restrict__ src,
                       float* __restrict__ wl, unsigned short* __restrict__ sl,
                       int* __restrict__ cnt, int n)
{
    int node = blockIdx.x * 8 + (threadIdx.x >> 5);
    if (node >= n) return;
    int lane = threadIdx.x & 31;
    int h = lane >> 2;
    int q = lane & 3;
    int fo = h * HDD + q * 4;

    int myv = 0;
    if (lane < DD) myv = src[(size_t)node * DD + lane];

    float4 ftv = *(const float4*)&fht[(size_t)node * FST + 128 + fo];
    float4 atv = *(const float4*)&attn[fo];

    float a[4];
    #pragma unroll
    for (int d = 0; d < DD; ++d) {
        int sd = __shfl_sync(0xffffffffu, myv, d);
        float4 fv = *(const float4*)&fht[(size_t)sd * FST + fo];
        float e, p = 0.f;
        e = fv.x + ftv.x; e = (e >= 0.f) ? e : SLOPEC * e; p += e * atv.x;
        e = fv.y + ftv.y; e = (e >= 0.f) ? e : SLOPEC * e; p += e * atv.y;
        e = fv.z + ftv.z; e = (e >= 0.f) ? e : SLOPEC * e; p += e * atv.z;
        e = fv.w + ftv.w; e = (e >= 0.f) ? e : SLOPEC * e; p += e * atv.w;
        p += __shfl_xor_sync(0xffffffffu, p, 1);
        p += __shfl_xor_sync(0xffffffffu, p, 2);
        if ((d >> 2) == q) a[d & 3] = p * SCORE_SCALE;
    }

    float m = fmaxf(fmaxf(a[0], a[1]), fmaxf(a[2], a[3]));
    m = fmaxf(m, __shfl_xor_sync(0xffffffffu, m, 1));
    m = fmaxf(m, __shfl_xor_sync(0xffffffffu, m, 2));
    float an[4];
    float ls = 0.f;
    #pragma unroll
    for (int j = 0; j < 4; ++j) { an[j] = expf(a[j] - m); ls += an[j]; }
    ls += __shfl_xor_sync(0xffffffffu, ls, 1);
    ls += __shfl_xor_sync(0xffffffffu, ls, 2);
    float inv = 1.f / ls;
    #pragma unroll
    for (int j = 0; j < 4; ++j) an[j] *= inv;

    unsigned alive = 0xFu;
    float thr = 0.f;
    #pragma unroll
    for (int it = 0; it < 5; ++it) {
        float lm = -1.f;
        #pragma unroll
        for (int j = 0; j < 4; ++j)
            if (alive & (1u << j)) lm = fmaxf(lm, an[j]);
        float gm = lm;
        gm = fmaxf(gm, __shfl_xor_sync(0xffffffffu, gm, 1));
        gm = fmaxf(gm, __shfl_xor_sync(0xffffffffu, gm, 2));
        thr = gm;
        int ld = 64;
        #pragma unroll
        for (int j = 3; j >= 0; --j)
            if ((alive & (1u << j)) && an[j] == gm) ld = q * 4 + j;
        int gd = ld;
        gd = min(gd, __shfl_xor_sync(0xffffffffu, gd, 1));
        gd = min(gd, __shfl_xor_sync(0xffffffffu, gd, 2));
        int loc = gd - q * 4;
        if (loc >= 0 && loc < 4) alive &= ~(1u << loc);
    }

    bool k[4];
    float ts = 0.f;
    int lcnt = 0;
    #pragma unroll
    for (int j = 0; j < 4; ++j) {
        k[j] = (an[j] >= thr);
        if (k[j]) { ts += an[j]; ++lcnt; }
    }
    ts += __shfl_xor_sync(0xffffffffu, ts, 1);
    ts += __shfl_xor_sync(0xffffffffu, ts, 2);
    float itn = 1.f / ts;

    int x = lcnt;
    int t1 = __shfl_up_sync(0xffffffffu, x, 1, 4);
    if (q >= 1) x += t1;
    int t2 = __shfl_up_sync(0xffffffffu, x, 2, 4);
    if (q >= 2) x += t2;
    int off = x - lcnt;
    int tot = __shfl_sync(0xffffffffu, x, 3, 4);

    int sj[4];
    #pragma unroll
    for (int j = 0; j < 4; ++j)
        sj[j] = __shfl_sync(0xffffffffu, myv, q * 4 + j);

    size_t base = ((size_t)node * HH + h) * 16;
    int pos = off;
    #pragma unroll
    for (int j = 0; j < 4; ++j) {
        if (k[j]) {
            wl[base + pos] = an[j] * itn;
            sl[base + pos] = (unsigned short)sj[j];
            ++pos;
        }
    }
    if (q == 0) cnt[(size_t)node * HH + h] = tot;
}

// ---------------------------------------------------------------------------
// Shared hop body (R10): predicated 8-way gathers + rare tail.
// ---------------------------------------------------------------------------
__device__ __forceinline__ float4 hop_acc(const float* __restrict__ hin,
                                          const float* __restrict__ wl,
                                          const unsigned short* __restrict__ sl,
                                          int c, size_t lb, int fo)
{
    float4 w0 = *(const float4*)&wl[lb];
    float4 w1 = *(const float4*)&wl[lb + 4];
    uint4  sp = *(const uint4*)&sl[lb];
    const unsigned short* sjp = (const unsigned short*)&sp;
    float wj[8] = {w0.x, w0.y, w0.z, w0.w, w1.x, w1.y, w1.z, w1.w};

    float4 acc = {0.f, 0.f, 0.f, 0.f};
    #pragma unroll
    for (int j = 0; j < 8; ++j) {
        if (j < c) {
            float4 v = *(const float4*)&hin[(size_t)sjp[j] * DIMC + fo];
            acc.x += wj[j] * v.x; acc.y += wj[j] * v.y;
            acc.z += wj[j] * v.z; acc.w += wj[j] * v.w;
        }
    }
    for (int j = 8; j < c; ++j) {
        float w = wl[lb + j];
        int   s = sl[lb + j];
        float4 v = *(const float4*)&hin[(size_t)s * DIMC + fo];
        acc.x += w * v.x; acc.y += w * v.y; acc.z += w * v.z; acc.w += w * v.w;
    }
    return acc;
}

__global__ void k_hop(const float* __restrict__ hin, const float* __restrict__ fe,
                      const float* __restrict__ wl, const unsigned short* __restrict__ sl,
                      const int* __restrict__ cnt, float* __restrict__ hout, int n)
{
    int node = blockIdx.x * 8 + (threadIdx.x >> 5);
    if (node >= n) return;
    int lane = threadIdx.x & 31;
    int h = lane >> 2;
    int q = lane & 3;
    int fo = h * HDD + q * 4;

    size_t lb = ((size_t)node * HH + h) * 16;
    int c = cnt[(size_t)node * HH + h];

    float4 acc = hop_acc(hin, wl, sl, c, lb, fo);

    size_t o = (size_t)node * DIMC + fo;
    float4 f = *(const float4*)&fe[o];
    float4 r;
    r.x = (1.f - ALPHAC) * acc.x + ALPHAC * f.x;
    r.y = (1.f - ALPHAC) * acc.y + ALPHAC * f.y;
    r.z = (1.f - ALPHAC) * acc.z + ALPHAC * f.z;
    r.w = (1.f - ALPHAC) * acc.w + ALPHAC * f.w;
    *(float4*)&hout[o] = r;
}

// ---------------------------------------------------------------------------
// Final hop fused with residual add + LayerNorm2.
// ---------------------------------------------------------------------------
__global__ void k_hoplast(const float* __restrict__ hin, const float* __restrict__ fe,
                          const float* __restrict__ feat,
                          const float* __restrict__ g, const float* __restrict__ b,
                          const float* __restrict__ wl, const unsigned short* __restrict__ sl,
                          const int* __restrict__ cnt,
                          float* __restrict__ y, float* __restrict__ rst, int n)
{
    int node = blockIdx.x * 8 + (threadIdx.x >> 5);
    if (node >= n) return;
    int lane = threadIdx.x & 31;
    int h = lane >> 2;
    int q = lane & 3;
    int fo = h * HDD + q * 4;

    size_t lb = ((size_t)node * HH + h) * 16;
    int c = cnt[(size_t)node * HH + h];

    float4 acc = hop_acc(hin, wl, sl, c, lb, fo);

    size_t o = (size_t)node * DIMC + fo;
    float4 f  = *(const float4*)&fe[o];
    float4 ft = *(const float4*)&feat[o];
    float4 v;
    v.x = (1.f - ALPHAC) * acc.x + ALPHAC * f.x + ft.x;
    v.y = (1.f - ALPHAC) * acc.y + ALPHAC * f.y + ft.y;
    v.z = (1.f - ALPHAC) * acc.z + ALPHAC * f.z + ft.z;
    v.w = (1.f - ALPHAC) * acc.w + ALPHAC * f.w + ft.w;
    *(float4*)&rst[o] = v;

    float s = v.x + v.y + v.z + v.w;
    #pragma unroll
    for (int off = 16; off; off >>= 1) s += __shfl_xor_sync(0xffffffffu, s, off);
    float mu = s * (1.0f / 128.0f);

    float dx = v.x - mu, dy = v.y - mu, dz = v.z - mu, dw = v.w - mu;
    float vs = dx * dx + dy * dy + dz * dz + dw * dw;
    #pragma unroll
    for (int off = 16; off; off >>= 1) vs += __shfl_xor_sync(0xffffffffu, vs, off);
    float rs = rsqrtf(vs * (1.0f / 128.0f) + LNEPS);

    float4 gg = *(const float4*)&g[fo];
    float4 bb = *(const float4*)&b[fo];
    float4 o4;
    o4.x = dx * rs * gg.x + bb.x;
    o4.y = dy * rs * gg.y + bb.y;
    o4.z = dz * rs * gg.z + bb.z;
    o4.w = dw * rs * gg.w + bb.w;
    *(float4*)&y[o] = o4;
}

// ---------------------------------------------------------------------------
extern "C" void kernel_launch(void* const* d_in, const int* in_sizes, int n_in,
                              void* d_out, int out_size)
{
    const float* feat   = (const float*)d_in[0];
    const float* W_head = (const float*)d_in[1];
    const float* W_tail = (const float*)d_in[2];
    const float* W_ent  = (const float*)d_in[3];
    const float* attn   = (const float*)d_in[4];
    const float* g1     = (const float*)d_in[5];
    const float* b1     = (const float*)d_in[6];
    const float* g2     = (const float*)d_in[7];
    const float* b2     = (const float*)d_in[8];
    const float* W_ff1  = (const float*)d_in[9];
    const float* b_ff1  = (const float*)d_in[10];
    const float* W_ff2  = (const float*)d_in[11];
    const float* b_ff2  = (const float*)d_in[12];
    const int*   src    = (const int*)d_in[13];
    float* out = (float*)d_out;

    int n = in_sizes[0] / DIMC;   // 50000
    if (n > NNODES) n = NNODES;

    float* scratch = nullptr;
    cudaGetSymbolAddress((void**)&scratch, g_scratch);
    const size_t SZ = (size_t)NNODES * DIMC;
    float* xln    = scratch + 0 * SZ;
    float* fht    = scratch + 1 * SZ;          // N*256: fh|ft packed
    float* fe     = scratch + 3 * SZ;          // N*128 dense
    float* h0     = scratch + 4 * SZ;
    float* h1     = scratch + 5 * SZ;
    float* rst    = scratch + 6 * SZ;
    float* y      = scratch + 7 * SZ;
    float* wlist  = scratch + 8 * SZ;          // N*8*16 floats
    unsigned short* slist = (unsigned short*)(scratch + 9 * SZ); // N*8*16 u16
    int*   cnt    = (int*)(scratch + 10 * SZ); // N*8

    cudaFuncSetAttribute(k_gemm_tc, cudaFuncAttributeMaxDynamicSharedMemorySize,
                         GEMM_SMEM_BYTES);
    cudaFuncSetAttribute(k_ffn, cudaFuncAttributeMaxDynamicSharedMemorySize,
                         FFN_SMEM_BYTES);

    int lnGrid  = (n + 7) / 8;
    int mTiles  = (n + 127) / 128;
    int w8Grid  = (n + 7) / 8;

    // 1) x = LN(feat)
    k_ln<<<lnGrid, 256>>>(feat, nullptr, g1, b1, xln, nullptr, n);

    // 2) fused projection: tiles 0,1 -> fht [N,256]; tile 2 -> fe dense
    dim3 gp(3, mTiles);
    k_gemm_tc<<<gp, 256, GEMM_SMEM_BYTES>>>(xln, W_head, W_tail, W_ent,
                                            fht, fe, n, 128, 128, 256);

    // 3) attention -> compact top-k SoA lists
    k_attn<<<w8Grid, 256>>>(fht, attn, src, wlist, slist, cnt, n);

    // 4) 4 plain hops + final fused hop (hop5 + residual + LN2)
    k_hop<<<w8Grid, 256>>>(fe, fe, wlist, slist, cnt, h0, n);
    k_hop<<<w8Grid, 256>>>(h0, fe, wlist, slist, cnt, h1, n);
    k_hop<<<w8Grid, 256>>>(h1, fe, wlist, slist, cnt, h0, n);
    k_hop<<<w8Grid, 256>>>(h0, fe, wlist, slist, cnt, h1, n);
    k_hoplast<<<w8Grid, 256>>>(h1, fe, feat, g2, b2, wlist, slist, cnt, y, rst, n);

    // 5) fused FFN v3 (512 threads, register-prefetched W chunks)
    k_ffn<<<mTiles, 512, FFN_SMEM_BYTES>>>(y, W_ff1, b_ff1, W_ff2, b_ff2,
                                           rst, out, n);
}

// round 16
// speedup vs baseline: 1.0064x; 1.0064x over previous
#include <cuda_runtime.h>
#include <cuda_bf16.h>
#include <math.h>
#include <stdint.h>

#define NNODES 50000
#define DIMC   128
#define DD     16
#define HH     8
#define HDD    16
#define SLOPEC 0.2f
#define ALPHAC 0.1f
#define LNEPS  1e-5f
// ln(17)/16
#define SCORE_SCALE 0.17707583400351351f

// Scratch: 15*N*128 floats (~384MB)
__device__ float g_scratch[(size_t)NNODES * 1920];

__device__ __forceinline__ void bfsplit(float v0, float v1, uint32_t& hi, uint32_t& lo) {
    __nv_bfloat16 h0 = __float2bfloat16(v0);
    __nv_bfloat16 h1 = __float2bfloat16(v1);
    float r0 = v0 - __bfloat162float(h0);
    float r1 = v1 - __bfloat162float(h1);
    __nv_bfloat16 l0 = __float2bfloat16(r0);
    __nv_bfloat16 l1 = __float2bfloat16(r1);
    hi = ((uint32_t)__bfloat16_as_ushort(h1) << 16) | (uint32_t)__bfloat16_as_ushort(h0);
    lo = ((uint32_t)__bfloat16_as_ushort(l1) << 16) | (uint32_t)__bfloat16_as_ushort(l0);
}

__device__ __forceinline__ void mma16(float* c, const uint32_t* a, const uint32_t* b) {
    asm volatile("mma.sync.aligned.m16n8k16.row.col.f32.bf16.bf16.f32 "
        "{%0,%1,%2,%3}, {%4,%5,%6,%7}, {%8,%9}, {%0,%1,%2,%3};\n"
        : "+f"(c[0]), "+f"(c[1]), "+f"(c[2]), "+f"(c[3])
        : "r"(a[0]), "r"(a[1]), "r"(a[2]), "r"(a[3]), "r"(b[0]), "r"(b[1]));
}

// ---------------------------------------------------------------------------
// LayerNorm (optionally in+add, optionally store the pre-LN sum)
// ---------------------------------------------------------------------------
__global__ void k_ln(const float* __restrict__ in, const float* __restrict__ add,
                     const float* __restrict__ g, const float* __restrict__ b,
                     float* __restrict__ out, float* __restrict__ sum_out, int n)
{
    int row  = blockIdx.x * 8 + (threadIdx.x >> 5);
    int lane = threadIdx.x & 31;
    if (row >= n) return;

    float4 v = ((const float4*)in)[(size_t)row * 32 + lane];
    if (add) {
        float4 w = ((const float4*)add)[(size_t)row * 32 + lane];
        v.x += w.x; v.y += w.y; v.z += w.z; v.w += w.w;
    }
    if (sum_out) ((float4*)sum_out)[(size_t)row * 32 + lane] = v;

    float s = v.x + v.y + v.z + v.w;
    #pragma unroll
    for (int o = 16; o; o >>= 1) s += __shfl_xor_sync(0xffffffffu, s, o);
    float mu = s * (1.0f / 128.0f);

    float dx = v.x - mu, dy = v.y - mu, dz = v.z - mu, dw = v.w - mu;
    float vs = dx * dx + dy * dy + dz * dz + dw * dw;
    #pragma unroll
    for (int o = 16; o; o >>= 1) vs += __shfl_xor_sync(0xffffffffu, vs, o);
    float rs = rsqrtf(vs * (1.0f / 128.0f) + LNEPS);

    float4 gg = ((const float4*)g)[lane];
    float4 bb = ((const float4*)b)[lane];
    float4 o4;
    o4.x = dx * rs * gg.x + bb.x;
    o4.y = dy * rs * gg.y + bb.y;
    o4.z = dz * rs * gg.z + bb.z;
    o4.w = dw * rs * gg.w + bb.w;
    ((float4*)out)[(size_t)row * 32 + lane] = o4;
}

// ---------------------------------------------------------------------------
// Projection GEMM: R10-proven bf16x3 (m16n8k16), A+B fp32 split in-kernel.
// Block 128x128, BK=32, double-buffered, 8 warps (4x2), 2 CTAs/SM.
// ---------------------------------------------------------------------------
#define BK      32
#define A_STR2  20
#define B_STR2  136
#define STG_U32 (2*128*A_STR2 + 2*(BK/2)*B_STR2)
#define GEMM_SMEM_BYTES (2*STG_U32*4)

__global__ void __launch_bounds__(256, 2)
k_gemm_tc(const float* __restrict__ A,
          const float* __restrict__ B0, const float* __restrict__ B1,
          const float* __restrict__ B2,
          float* __restrict__ C, float* __restrict__ C2,
          int M, int K, int bNc, int cNc)
{
    extern __shared__ uint32_t smu[];

    int tid  = threadIdx.x;
    int warp = tid >> 5;
    int lane = tid & 31;
    int g    = lane >> 2;
    int tq   = lane & 3;
    int wr   = (warp >> 1) * 32;
    int wc   = (warp & 1) * 64;

    int row0 = blockIdx.y * 128;
    int c0   = blockIdx.x * 128;
    int bi   = c0 / bNc;
    const float* B = (bi == 0) ? B0 : ((bi == 1) ? B1 : B2);
    int bc0  = c0 - bi * bNc;

    int ar = tid >> 3;
    int ak = (tid & 7) << 2;

    float acc[2][8][4] = {};
    float4 pa[4];
    float4 pb0[2], pb1[2];

    int nch = K >> 5;

    #pragma unroll
    for (int s = 0; s < 4; ++s) {
        int node = row0 + ar + s * 32;
        pa[s] = (node < M) ? *(const float4*)&A[(size_t)node * K + ak]
                           : make_float4(0.f, 0.f, 0.f, 0.f);
    }
    #pragma unroll
    for (int s = 0; s < 2; ++s) {
        int slot = tid + s * 256;
        int kp = slot >> 5;
        int cc = (slot & 31) << 2;
        pb0[s] = *(const float4*)&B[(size_t)(2 * kp)     * bNc + bc0 + cc];
        pb1[s] = *(const float4*)&B[(size_t)(2 * kp + 1) * bNc + bc0 + cc];
    }
    {
        uint32_t* AsHi = smu;
        uint32_t* AsLo = AsHi + 128 * A_STR2;
        uint32_t* BsHi = AsLo + 128 * A_STR2;
        uint32_t* BsLo = BsHi + (BK/2) * B_STR2;
        #pragma unroll
        for (int s = 0; s < 4; ++s) {
            int r = ar + s * 32;
            uint32_t h0, l0, h1, l1;
            bfsplit(pa[s].x, pa[s].y, h0, l0);
            bfsplit(pa[s].z, pa[s].w, h1, l1);
            *(uint2*)&AsHi[r * A_STR2 + (ak >> 1)] = make_uint2(h0, h1);
            *(uint2*)&AsLo[r * A_STR2 + (ak >> 1)] = make_uint2(l0, l1);
        }
        #pragma unroll
        for (int s = 0; s < 2; ++s) {
            int slot = tid + s * 256;
            int kp = slot >> 5;
            int cc = (slot & 31) << 2;
            uint32_t h[4], l[4];
            bfsplit(pb0[s].x, pb1[s].x, h[0], l[0]);
            bfsplit(pb0[s].y, pb1[s].y, h[1], l[1]);
            bfsplit(pb0[s].z, pb1[s].z, h[2], l[2]);
            bfsplit(pb0[s].w, pb1[s].w, h[3], l[3]);
            *(uint4*)&BsHi[kp * B_STR2 + cc] = make_uint4(h[0], h[1], h[2], h[3]);
            *(uint4*)&BsLo[kp * B_STR2 + cc] = make_uint4(l[0], l[1], l[2], l[3]);
        }
    }
    __syncthreads();

    for (int ch = 0; ch < nch; ++ch) {
        int cur = ch & 1;
        uint32_t* AsHi = smu + cur * STG_U32;
        uint32_t* AsLo = AsHi + 128 * A_STR2;
        uint32_t* BsHi = AsLo + 128 * A_STR2;
        uint32_t* BsLo = BsHi + (BK/2) * B_STR2;

        bool more = (ch + 1) < nch;
        if (more) {
            int k0 = (ch + 1) << 5;
            #pragma unroll
            for (int s = 0; s < 4; ++s) {
                int node = row0 + ar + s * 32;
                pa[s] = (node < M) ? *(const float4*)&A[(size_t)node * K + k0 + ak]
                                   : make_float4(0.f, 0.f, 0.f, 0.f);
            }
            #pragma unroll
            for (int s = 0; s < 2; ++s) {
                int slot = tid + s * 256;
                int kp = slot >> 5;
                int cc = (slot & 31) << 2;
                pb0[s] = *(const float4*)&B[(size_t)(k0 + 2 * kp)     * bNc + bc0 + cc];
                pb1[s] = *(const float4*)&B[(size_t)(k0 + 2 * kp + 1) * bNc + bc0 + cc];
            }
        }

        #pragma unroll
        for (int ks = 0; ks < 2; ++ks) {
            int kb = ks * 8;
            uint32_t ahi[2][4], alo[2][4];
            #pragma unroll
            for (int mf = 0; mf < 2; ++mf) {
                int r = wr + mf * 16 + g;
                ahi[mf][0] = AsHi[r * A_STR2 + kb + tq];
                ahi[mf][1] = AsHi[(r + 8) * A_STR2 + kb + tq];
                ahi[mf][2] = AsHi[r * A_STR2 + kb + tq + 4];
                ahi[mf][3] = AsHi[(r + 8) * A_STR2 + kb + tq + 4];
                alo[mf][0] = AsLo[r * A_STR2 + kb + tq];
                alo[mf][1] = AsLo[(r + 8) * A_STR2 + kb + tq];
                alo[mf][2] = AsLo[r * A_STR2 + kb + tq + 4];
                alo[mf][3] = AsLo[(r + 8) * A_STR2 + kb + tq + 4];
            }
            #pragma unroll
            for (int nf = 0; nf < 8; ++nf) {
                int c = wc + nf * 8 + g;
                uint32_t bhi[2], blo[2];
                bhi[0] = BsHi[(kb + tq) * B_STR2 + c];
                bhi[1] = BsHi[(kb + tq + 4) * B_STR2 + c];
                blo[0] = BsLo[(kb + tq) * B_STR2 + c];
                blo[1] = BsLo[(kb + tq + 4) * B_STR2 + c];
                #pragma unroll
                for (int mf = 0; mf < 2; ++mf) {
                    mma16(acc[mf][nf], ahi[mf], bhi);
                    mma16(acc[mf][nf], ahi[mf], blo);
                    mma16(acc[mf][nf], alo[mf], bhi);
                }
            }
        }

        if (more) {
            uint32_t* nAsHi = smu + (cur ^ 1) * STG_U32;
            uint32_t* nAsLo = nAsHi + 128 * A_STR2;
            uint32_t* nBsHi = nAsLo + 128 * A_STR2;
            uint32_t* nBsLo = nBsHi + (BK/2) * B_STR2;
            #pragma unroll
            for (int s = 0; s < 4; ++s) {
                int r = ar + s * 32;
                uint32_t h0, l0, h1, l1;
                bfsplit(pa[s].x, pa[s].y, h0, l0);
                bfsplit(pa[s].z, pa[s].w, h1, l1);
                *(uint2*)&nAsHi[r * A_STR2 + (ak >> 1)] = make_uint2(h0, h1);
                *(uint2*)&nAsLo[r * A_STR2 + (ak >> 1)] = make_uint2(l0, l1);
            }
            #pragma unroll
            for (int s = 0; s < 2; ++s) {
                int slot = tid + s * 256;
                int kp = slot >> 5;
                int cc = (slot & 31) << 2;
                uint32_t h[4], l[4];
                bfsplit(pb0[s].x, pb1[s].x, h[0], l[0]);
                bfsplit(pb0[s].y, pb1[s].y, h[1], l[1]);
                bfsplit(pb0[s].z, pb1[s].z, h[2], l[2]);
                bfsplit(pb0[s].w, pb1[s].w, h[3], l[3]);
                *(uint4*)&nBsHi[kp * B_STR2 + cc] = make_uint4(h[0], h[1], h[2], h[3]);
                *(uint4*)&nBsLo[kp * B_STR2 + cc] = make_uint4(l[0], l[1], l[2], l[3]);
            }
            __syncthreads();
        }
    }

    float* Co = C;
    int ostr  = cNc;
    int ocol0 = c0;
    if (C2 && bi == 2) { Co = C2; ostr = 128; ocol0 = bc0; }

    #pragma unroll
    for (int mf = 0; mf < 2; ++mf) {
        #pragma unroll
        for (int nf = 0; nf < 8; ++nf) {
            int col = ocol0 + wc + nf * 8 + 2 * tq;
            #pragma unroll
            for (int half = 0; half < 2; ++half) {
                int row = row0 + wr + mf * 16 + g + half * 8;
                if (row >= M) continue;
                float2 r;
                r.x = acc[mf][nf][half * 2 + 0];
                r.y = acc[mf][nf][half * 2 + 1];
                *(float2*)&Co[(size_t)row * ostr + col] = r;
            }
        }
    }
}

// ---------------------------------------------------------------------------
// Fused FFN (R14 form): 512 threads (16 warps, 4x4), warp tile 32x32.
// out = relu(y @ W1 + b1) @ W2 + b2 + rst; hidden never hits DRAM.
// ---------------------------------------------------------------------------
#define YA_STR 68
#define WB_STR 136
#define Y_PL   (128 * YA_STR)
#define W_PL   (64 * WB_STR)
#define FFN_SMEM_BYTES ((2*Y_PL + 2*W_PL + 2*Y_PL) * 4)

__device__ __forceinline__ void ffn_mma_block(const uint32_t* AH, const uint32_t* AL,
                                              const uint32_t* BH, const uint32_t* BL,
                                              float acc[2][4][4],
                                              int wr, int wc, int g, int tq)
{
    #pragma unroll
    for (int ks = 0; ks < 8; ++ks) {
        int kb = ks * 8;
        uint32_t ahi[2][4], alo[2][4];
        #pragma unroll
        for (int mf = 0; mf < 2; ++mf) {
            int r = wr + mf * 16 + g;
            ahi[mf][0] = AH[r * YA_STR + kb + tq];
            ahi[mf][1] = AH[(r + 8) * YA_STR + kb + tq];
            ahi[mf][2] = AH[r * YA_STR + kb + tq + 4];
            ahi[mf][3] = AH[(r + 8) * YA_STR + kb + tq + 4];
            alo[mf][0] = AL[r * YA_STR + kb + tq];
            alo[mf][1] = AL[(r + 8) * YA_STR + kb + tq];
            alo[mf][2] = AL[r * YA_STR + kb + tq + 4];
            alo[mf][3] = AL[(r + 8) * YA_STR + kb + tq + 4];
        }
        #pragma unroll
        for (int nf = 0; nf < 4; ++nf) {
            int c = wc + nf * 8 + g;
            uint32_t bhi[2], blo[2];
            bhi[0] = BH[(kb + tq) * WB_STR + c];
            bhi[1] = BH[(kb + tq + 4) * WB_STR + c];
            blo[0] = BL[(kb + tq) * WB_STR + c];
            blo[1] = BL[(kb + tq + 4) * WB_STR + c];
            #pragma unroll
            for (int mf = 0; mf < 2; ++mf) {
                mma16(acc[mf][nf], ahi[mf], bhi);
                mma16(acc[mf][nf], ahi[mf], blo);
                mma16(acc[mf][nf], alo[mf], bhi);
            }
        }
    }
}

__device__ __forceinline__ void ffn_load_w(const float* __restrict__ W, int ldw,
                                           int row_off, int col_off,
                                           uint32_t* BH, uint32_t* BL, int tid)
{
    #pragma unroll
    for (int s = 0; s < 4; ++s) {
        int slot = tid + s * 512;
        int kp = slot >> 5;
        int c4 = (slot & 31) << 2;
        float4 a = *(const float4*)&W[(size_t)(row_off + 2 * kp)     * ldw + col_off + c4];
        float4 b = *(const float4*)&W[(size_t)(row_off + 2 * kp + 1) * ldw + col_off + c4];
        uint32_t h[4], l[4];
        bfsplit(a.x, b.x, h[0], l[0]);
        bfsplit(a.y, b.y, h[1], l[1]);
        bfsplit(a.z, b.z, h[2], l[2]);
        bfsplit(a.w, b.w, h[3], l[3]);
        *(uint4*)&BH[kp * WB_STR + c4] = make_uint4(h[0], h[1], h[2], h[3]);
        *(uint4*)&BL[kp * WB_STR + c4] = make_uint4(l[0], l[1], l[2], l[3]);
    }
}

__global__ void __launch_bounds__(512, 1)
k_ffn(const float* __restrict__ Yg, const float* __restrict__ W1,
      const float* __restrict__ b1, const float* __restrict__ W2,
      const float* __restrict__ b2, const float* __restrict__ rst,
      float* __restrict__ out, int M)
{
    extern __shared__ uint32_t smu[];
    uint32_t* YH = smu;
    uint32_t* YL = YH + Y_PL;
    uint32_t* WH = YL + Y_PL;
    uint32_t* WL = WH + W_PL;
    uint32_t* HH2 = WL + W_PL;
    uint32_t* HL2 = HH2 + Y_PL;

    int tid  = threadIdx.x;
    int warp = tid >> 5;
    int lane = tid & 31;
    int g    = lane >> 2;
    int tq   = lane & 3;
    int wr   = (warp >> 2) * 32;
    int wc   = (warp & 3) * 32;
    int row0 = blockIdx.x * 128;

    // ---- load y rows -> Y planes (once) ----
    #pragma unroll
    for (int s = 0; s < 4; ++s) {
        int slot = tid + s * 512;
        int r = slot >> 4;
        int i = slot & 15;
        int node = row0 + r;
        float4 v  = make_float4(0.f, 0.f, 0.f, 0.f);
        float4 v2 = make_float4(0.f, 0.f, 0.f, 0.f);
        if (node < M) {
            v  = *(const float4*)&Yg[(size_t)node * DIMC + i * 8];
            v2 = *(const float4*)&Yg[(size_t)node * DIMC + i * 8 + 4];
        }
        uint32_t h0, l0, h1, l1, h2, l2, h3, l3;
        bfsplit(v.x,  v.y,  h0, l0);
        bfsplit(v.z,  v.w,  h1, l1);
        bfsplit(v2.x, v2.y, h2, l2);
        bfsplit(v2.z, v2.w, h3, l3);
        *(uint4*)&YH[r * YA_STR + i * 4] = make_uint4(h0, h1, h2, h3);
        *(uint4*)&YL[r * YA_STR + i * 4] = make_uint4(l0, l1, l2, l3);
    }

    float accO[2][4][4] = {};

    #pragma unroll 1
    for (int cc = 0; cc < 4; ++cc) {
        int hc0 = cc * 128;

        ffn_load_w(W1, 512, 0, hc0, WH, WL, tid);
        __syncthreads();

        float accH[2][4][4] = {};
        ffn_mma_block(YH, YL, WH, WL, accH, wr, wc, g, tq);
        __syncthreads();

        #pragma unroll
        for (int mf = 0; mf < 2; ++mf) {
            #pragma unroll
            for (int nf = 0; nf < 4; ++nf) {
                int col = wc + nf * 8 + 2 * tq;
                float bx = b1[hc0 + col];
                float by = b1[hc0 + col + 1];
                #pragma unroll
                for (int half = 0; half < 2; ++half) {
                    int row = wr + mf * 16 + g + half * 8;
                    float rx = fmaxf(accH[mf][nf][half * 2 + 0] + bx, 0.f);
                    float ry = fmaxf(accH[mf][nf][half * 2 + 1] + by, 0.f);
                    uint32_t hh, ll;
                    bfsplit(rx, ry, hh, ll);
                    HH2[row * YA_STR + (col >> 1)] = hh;
                    HL2[row * YA_STR + (col >> 1)] = ll;
                }
            }
        }

        ffn_load_w(W2, 128, hc0, 0, WH, WL, tid);
        __syncthreads();

        ffn_mma_block(HH2, HL2, WH, WL, accO, wr, wc, g, tq);
        __syncthreads();
    }

    #pragma unroll
    for (int mf = 0; mf < 2; ++mf) {
        #pragma unroll
        for (int nf = 0; nf < 4; ++nf) {
            int col = wc + nf * 8 + 2 * tq;
            float bx = b2[col];
            float by = b2[col + 1];
            #pragma unroll
            for (int half = 0; half < 2; ++half) {
                int row = row0 + wr + mf * 16 + g + half * 8;
                if (row >= M) continue;
                size_t base = (size_t)row * DIMC + col;
                float2 av = *(const float2*)&rst[base];
                float2 r;
                r.x = accO[mf][nf][half * 2 + 0] + bx + av.x;
                r.y = accO[mf][nf][half * 2 + 1] + by + av.y;
                *(float2*)&out[base] = r;
            }
        }
    }
}

// ---------------------------------------------------------------------------
// Attention v3 (R10): one WARP per node. Emits SoA lists wl[16] fp32 /
// sl[16] u16 per (node, head) + cnt.
// ---------------------------------------------------------------------------
#define FST 256

__global__ void k_attn(const float* __restrict__ fht, const float* __restrict__ attn,
                       const int* __restrict__ src,
                       float* __restrict__ wl, unsigned short* __restrict__ sl,
                       int* __restrict__ cnt, int n)
{
    int node = blockIdx.x * 8 + (threadIdx.x >> 5);
    if (node >= n) return;
    int lane = threadIdx.x & 31;
    int h = lane >> 2;
    int q = lane & 3;
    int fo = h * HDD + q * 4;

    int myv = 0;
    if (lane < DD) myv = src[(size_t)node * DD + lane];

    float4 ftv = *(const float4*)&fht[(size_t)node * FST + 128 + fo];
    float4 atv = *(const float4*)&attn[fo];

    float a[4];
    #pragma unroll
    for (int d = 0; d < DD; ++d) {
        int sd = __shfl_sync(0xffffffffu, myv, d);
        float4 fv = *(const float4*)&fht[(size_t)sd * FST + fo];
        float e, p = 0.f;
        e = fv.x + ftv.x; e = (e >= 0.f) ? e : SLOPEC * e; p += e * atv.x;
        e = fv.y + ftv.y; e = (e >= 0.f) ? e : SLOPEC * e; p += e * atv.y;
        e = fv.z + ftv.z; e = (e >= 0.f) ? e : SLOPEC * e; p += e * atv.z;
        e = fv.w + ftv.w; e = (e >= 0.f) ? e : SLOPEC * e; p += e * atv.w;
        p += __shfl_xor_sync(0xffffffffu, p, 1);
        p += __shfl_xor_sync(0xffffffffu, p, 2);
        if ((d >> 2) == q) a[d & 3] = p * SCORE_SCALE;
    }

    float m = fmaxf(fmaxf(a[0], a[1]), fmaxf(a[2], a[3]));
    m = fmaxf(m, __shfl_xor_sync(0xffffffffu, m, 1));
    m = fmaxf(m, __shfl_xor_sync(0xffffffffu, m, 2));
    float an[4];
    float ls = 0.f;
    #pragma unroll
    for (int j = 0; j < 4; ++j) { an[j] = expf(a[j] - m); ls += an[j]; }
    ls += __shfl_xor_sync(0xffffffffu, ls, 1);
    ls += __shfl_xor_sync(0xffffffffu, ls, 2);
    float inv = 1.f / ls;
    #pragma unroll
    for (int j = 0; j < 4; ++j) an[j] *= inv;

    unsigned alive = 0xFu;
    float thr = 0.f;
    #pragma unroll
    for (int it = 0; it < 5; ++it) {
        float lm = -1.f;
        #pragma unroll
        for (int j = 0; j < 4; ++j)
            if (alive & (1u << j)) lm = fmaxf(lm, an[j]);
        float gm = lm;
        gm = fmaxf(gm, __shfl_xor_sync(0xffffffffu, gm, 1));
        gm = fmaxf(gm, __shfl_xor_sync(0xffffffffu, gm, 2));
        thr = gm;
        int ld = 64;
        #pragma unroll
        for (int j = 3; j >= 0; --j)
            if ((alive & (1u << j)) && an[j] == gm) ld = q * 4 + j;
        int gd = ld;
        gd = min(gd, __shfl_xor_sync(0xffffffffu, gd, 1));
        gd = min(gd, __shfl_xor_sync(0xffffffffu, gd, 2));
        int loc = gd - q * 4;
        if (loc >= 0 && loc < 4) alive &= ~(1u << loc);
    }

    bool k[4];
    float ts = 0.f;
    int lcnt = 0;
    #pragma unroll
    for (int j = 0; j < 4; ++j) {
        k[j] = (an[j] >= thr);
        if (k[j]) { ts += an[j]; ++lcnt; }
    }
    ts += __shfl_xor_sync(0xffffffffu, ts, 1);
    ts += __shfl_xor_sync(0xffffffffu, ts, 2);
    float itn = 1.f / ts;

    int x = lcnt;
    int t1 = __shfl_up_sync(0xffffffffu, x, 1, 4);
    if (q >= 1) x += t1;
    int t2 = __shfl_up_sync(0xffffffffu, x, 2, 4);
    if (q >= 2) x += t2;
    int off = x - lcnt;
    int tot = __shfl_sync(0xffffffffu, x, 3, 4);

    int sj[4];
    #pragma unroll
    for (int j = 0; j < 4; ++j)
        sj[j] = __shfl_sync(0xffffffffu, myv, q * 4 + j);

    size_t base = ((size_t)node * HH + h) * 16;
    int pos = off;
    #pragma unroll
    for (int j = 0; j < 4; ++j) {
        if (k[j]) {
            wl[base + pos] = an[j] * itn;
            sl[base + pos] = (unsigned short)sj[j];
            ++pos;
        }
    }
    if (q == 0) cnt[(size_t)node * HH + h] = tot;
}

// ---------------------------------------------------------------------------
// Hop v2: TWO nodes per warp. lane -> (node-half = lane/16, h = (lane%16)/2,
// 8-float half-row = (lane%2)*8). Each lane issues 2 independent float4
// gathers per list entry -> 2x MLP per thread at equal bytes.
// ---------------------------------------------------------------------------
__device__ __forceinline__ void hop_acc8(const float* __restrict__ hin,
                                         const float* __restrict__ wl,
                                         const unsigned short* __restrict__ sl,
                                         int c, size_t lb, int fo,
                                         float4& acc0, float4& acc1)
{
    float4 w0 = *(const float4*)&wl[lb];
    float4 w1 = *(const float4*)&wl[lb + 4];
    uint4  sp = *(const uint4*)&sl[lb];
    const unsigned short* sjp = (const unsigned short*)&sp;
    float wj[8] = {w0.x, w0.y, w0.z, w0.w, w1.x, w1.y, w1.z, w1.w};

    acc0 = make_float4(0.f, 0.f, 0.f, 0.f);
    acc1 = make_float4(0.f, 0.f, 0.f, 0.f);
    #pragma unroll
    for (int j = 0; j < 8; ++j) {
        if (j < c) {
            const float* rp = &hin[(size_t)sjp[j] * DIMC + fo];
            float4 v0 = *(const float4*)rp;
            float4 v1 = *(const float4*)(rp + 4);
            acc0.x += wj[j] * v0.x; acc0.y += wj[j] * v0.y;
            acc0.z += wj[j] * v0.z; acc0.w += wj[j] * v0.w;
            acc1.x += wj[j] * v1.x; acc1.y += wj[j] * v1.y;
            acc1.z += wj[j] * v1.z; acc1.w += wj[j] * v1.w;
        }
    }
    for (int j = 8; j < c; ++j) {
        float w = wl[lb + j];
        int   s = sl[lb + j];
        const float* rp = &hin[(size_t)s * DIMC + fo];
        float4 v0 = *(const float4*)rp;
        float4 v1 = *(const float4*)(rp + 4);
        acc0.x += w * v0.x; acc0.y += w * v0.y; acc0.z += w * v0.z; acc0.w += w * v0.w;
        acc1.x += w * v1.x; acc1.y += w * v1.y; acc1.z += w * v1.z; acc1.w += w * v1.w;
    }
}

__global__ void k_hop(const float* __restrict__ hin, const float* __restrict__ fe,
                      const float* __restrict__ wl, const unsigned short* __restrict__ sl,
                      const int* __restrict__ cnt, float* __restrict__ hout, int n)
{
    int lane = threadIdx.x & 31;
    int il   = lane & 15;
    int node = blockIdx.x * 16 + (threadIdx.x >> 5) * 2 + (lane >> 4);
    if (node >= n) return;
    int h  = il >> 1;
    int fo = h * HDD + ((il & 1) << 3);

    size_t lb = ((size_t)node * HH + h) * 16;
    int c = cnt[(size_t)node * HH + h];

    float4 a0, a1;
    hop_acc8(hin, wl, sl, c, lb, fo, a0, a1);

    size_t o = (size_t)node * DIMC + fo;
    float4 f0 = *(const float4*)&fe[o];
    float4 f1 = *(const float4*)&fe[o + 4];
    float4 r0, r1;
    r0.x = (1.f - ALPHAC) * a0.x + ALPHAC * f0.x;
    r0.y = (1.f - ALPHAC) * a0.y + ALPHAC * f0.y;
    r0.z = (1.f - ALPHAC) * a0.z + ALPHAC * f0.z;
    r0.w = (1.f - ALPHAC) * a0.w + ALPHAC * f0.w;
    r1.x = (1.f - ALPHAC) * a1.x + ALPHAC * f1.x;
    r1.y = (1.f - ALPHAC) * a1.y + ALPHAC * f1.y;
    r1.z = (1.f - ALPHAC) * a1.z + ALPHAC * f1.z;
    r1.w = (1.f - ALPHAC) * a1.w + ALPHAC * f1.w;
    *(float4*)&hout[o]     = r0;
    *(float4*)&hout[o + 4] = r1;
}

// ---------------------------------------------------------------------------
// Final hop fused with residual add + LayerNorm2 (2 nodes/warp; LN reduction
// over 16-lane groups; invalid nodes clamped, stores predicated).
// ---------------------------------------------------------------------------
__global__ void k_hoplast(const float* __restrict__ hin, const float* __restrict__ fe,
                          const float* __restrict__ feat,
                          const float* __restrict__ g, const float* __restrict__ b,
                          const float* __restrict__ wl, const unsigned short* __restrict__ sl,
                          const int* __restrict__ cnt,
                          float* __restrict__ y, float* __restrict__ rst, int n)
{
    int lane = threadIdx.x & 31;
    int il   = lane & 15;
    int node = blockIdx.x * 16 + (threadIdx.x >> 5) * 2 + (lane >> 4);
    bool valid = (node < n);
    int nodec = valid ? node : (n - 1);
    int h  = il >> 1;
    int fo = h * HDD + ((il & 1) << 3);

    size_t lb = ((size_t)nodec * HH + h) * 16;
    int c = cnt[(size_t)nodec * HH + h];

    float4 a0, a1;
    hop_acc8(hin, wl, sl, c, lb, fo, a0, a1);

    size_t o = (size_t)nodec * DIMC + fo;
    float4 f0 = *(const float4*)&fe[o];
    float4 f1 = *(const float4*)&fe[o + 4];
    float4 t0 = *(const float4*)&feat[o];
    float4 t1 = *(const float4*)&feat[o + 4];
    float4 v0, v1;
    v0.x = (1.f - ALPHAC) * a0.x + ALPHAC * f0.x + t0.x;
    v0.y = (1.f - ALPHAC) * a0.y + ALPHAC * f0.y + t0.y;
    v0.z = (1.f - ALPHAC) * a0.z + ALPHAC * f0.z + t0.z;
    v0.w = (1.f - ALPHAC) * a0.w + ALPHAC * f0.w + t0.w;
    v1.x = (1.f - ALPHAC) * a1.x + ALPHAC * f1.x + t1.x;
    v1.y = (1.f - ALPHAC) * a1.y + ALPHAC * f1.y + t1.y;
    v1.z = (1.f - ALPHAC) * a1.z + ALPHAC * f1.z + t1.z;
    v1.w = (1.f - ALPHAC) * a1.w + ALPHAC * f1.w + t1.w;
    if (valid) {
        *(float4*)&rst[o]     = v0;
        *(float4*)&rst[o + 4] = v1;
    }

    // LN over the node's 128 values: 8 local + 16-lane group shuffles
    float s = v0.x + v0.y + v0.z + v0.w + v1.x + v1.y + v1.z + v1.w;
    #pragma unroll
    for (int off = 8; off; off >>= 1) s += __shfl_xor_sync(0xffffffffu, s, off);
    float mu = s * (1.0f / 128.0f);

    float d0x = v0.x - mu, d0y = v0.y - mu, d0z = v0.z - mu, d0w = v0.w - mu;
    float d1x = v1.x - mu, d1y = v1.y - mu, d1z = v1.z - mu, d1w = v1.w - mu;
    float vs = d0x * d0x + d0y * d0y + d0z * d0z + d0w * d0w
             + d1x * d1x + d1y * d1y + d1z * d1z + d1w * d1w;
    #pragma unroll
    for (int off = 8; off; off >>= 1) vs += __shfl_xor_sync(0xffffffffu, vs, off);
    float rsq = rsqrtf(vs * (1.0f / 128.0f) + LNEPS);

    float4 g0 = *(const float4*)&g[fo];
    float4 g1v = *(const float4*)&g[fo + 4];
    float4 b0 = *(const float4*)&b[fo];
    float4 b1v = *(const float4*)&b[fo + 4];
    float4 o0, o1;
    o0.x = d0x * rsq * g0.x + b0.x;
    o0.y = d0y * rsq * g0.y + b0.y;
    o0.z = d0z * rsq * g0.z + b0.z;
    o0.w = d0w * rsq * g0.w + b0.w;
    o1.x = d1x * rsq * g1v.x + b1v.x;
    o1.y = d1y * rsq * g1v.y + b1v.y;
    o1.z = d1z * rsq * g1v.z + b1v.z;
    o1.w = d1w * rsq * g1v.w + b1v.w;
    if (valid) {
        *(float4*)&y[o]     = o0;
        *(float4*)&y[o + 4] = o1;
    }
}

// ---------------------------------------------------------------------------
extern "C" void kernel_launch(void* const* d_in, const int* in_sizes, int n_in,
                              void* d_out, int out_size)
{
    const float* feat   = (const float*)d_in[0];
    const float* W_head = (const float*)d_in[1];
    const float* W_tail = (const float*)d_in[2];
    const float* W_ent  = (const float*)d_in[3];
    const float* attn   = (const float*)d_in[4];
    const float* g1     = (const float*)d_in[5];
    const float* b1     = (const float*)d_in[6];
    const float* g2     = (const float*)d_in[7];
    const float* b2     = (const float*)d_in[8];
    const float* W_ff1  = (const float*)d_in[9];
    const float* b_ff1  = (const float*)d_in[10];
    const float* W_ff2  = (const float*)d_in[11];
    const float* b_ff2  = (const float*)d_in[12];
    const int*   src    = (const int*)d_in[13];
    float* out = (float*)d_out;

    int n = in_sizes[0] / DIMC;   // 50000
    if (n > NNODES) n = NNODES;

    float* scratch = nullptr;
    cudaGetSymbolAddress((void**)&scratch, g_scratch);
    const size_t SZ = (size_t)NNODES * DIMC;
    float* xln    = scratch + 0 * SZ;
    float* fht    = scratch + 1 * SZ;          // N*256: fh|ft packed
    float* fe     = scratch + 3 * SZ;          // N*128 dense
    float* h0     = scratch + 4 * SZ;
    float* h1     = scratch + 5 * SZ;
    float* rst    = scratch + 6 * SZ;
    float* y      = scratch + 7 * SZ;
    float* wlist  = scratch + 8 * SZ;          // N*8*16 floats
    unsigned short* slist = (unsigned short*)(scratch + 9 * SZ); // N*8*16 u16
    int*   cnt    = (int*)(scratch + 10 * SZ); // N*8

    cudaFuncSetAttribute(k_gemm_tc, cudaFuncAttributeMaxDynamicSharedMemorySize,
                         GEMM_SMEM_BYTES);
    cudaFuncSetAttribute(k_ffn, cudaFuncAttributeMaxDynamicSharedMemorySize,
                         FFN_SMEM_BYTES);

    int lnGrid   = (n + 7) / 8;
    int mTiles   = (n + 127) / 128;
    int w8Grid   = (n + 7) / 8;
    int w16Grid  = (n + 15) / 16;

    // 1) x = LN(feat)
    k_ln<<<lnGrid, 256>>>(feat, nullptr, g1, b1, xln, nullptr, n);

    // 2) fused projection: tiles 0,1 -> fht [N,256]; tile 2 -> fe dense
    dim3 gp(3, mTiles);
    k_gemm_tc<<<gp, 256, GEMM_SMEM_BYTES>>>(xln, W_head, W_tail, W_ent,
                                            fht, fe, n, 128, 128, 256);

    // 3) attention -> compact top-k SoA lists
    k_attn<<<w8Grid, 256>>>(fht, attn, src, wlist, slist, cnt, n);

    // 4) 4 plain hops (2 nodes/warp) + final fused hop (hop5 + residual + LN2)
    k_hop<<<w16Grid, 256>>>(fe, fe, wlist, slist, cnt, h0, n);
    k_hop<<<w16Grid, 256>>>(h0, fe, wlist, slist, cnt, h1, n);
    k_hop<<<w16Grid, 256>>>(h1, fe, wlist, slist, cnt, h0, n);
    k_hop<<<w16Grid, 256>>>(h0, fe, wlist, slist, cnt, h1, n);
    k_hoplast<<<w16Grid, 256>>>(h1, fe, feat, g2, b2, wlist, slist, cnt, y, rst, n);

    // 5) fused FFN (R14 form): out = relu(y@W1+b1)@W2 + b2 + rst
    k_ffn<<<mTiles, 512, FFN_SMEM_BYTES>>>(y, W_ff1, b_ff1, W_ff2, b_ff2,
                                           rst, out, n);
}

// round 17
// speedup vs baseline: 1.0264x; 1.0199x over previous
#include <cuda_runtime.h>
#include <cuda_bf16.h>
#include <math.h>
#include <stdint.h>

#define NNODES 50000
#define DIMC   128
#define DD     16
#define HH     8
#define HDD    16
#define SLOPEC 0.2f
#define ALPHAC 0.1f
#define LNEPS  1e-5f
// ln(17)/16
#define SCORE_SCALE 0.17707583400351351f

// Scratch: 15*N*128 floats (~384MB)
__device__ float g_scratch[(size_t)NNODES * 1920];

__device__ __forceinline__ void bfsplit(float v0, float v1, uint32_t& hi, uint32_t& lo) {
    __nv_bfloat16 h0 = __float2bfloat16(v0);
    __nv_bfloat16 h1 = __float2bfloat16(v1);
    float r0 = v0 - __bfloat162float(h0);
    float r1 = v1 - __bfloat162float(h1);
    __nv_bfloat16 l0 = __float2bfloat16(r0);
    __nv_bfloat16 l1 = __float2bfloat16(r1);
    hi = ((uint32_t)__bfloat16_as_ushort(h1) << 16) | (uint32_t)__bfloat16_as_ushort(h0);
    lo = ((uint32_t)__bfloat16_as_ushort(l1) << 16) | (uint32_t)__bfloat16_as_ushort(l0);
}

__device__ __forceinline__ void mma16(float* c, const uint32_t* a, const uint32_t* b) {
    asm volatile("mma.sync.aligned.m16n8k16.row.col.f32.bf16.bf16.f32 "
        "{%0,%1,%2,%3}, {%4,%5,%6,%7}, {%8,%9}, {%0,%1,%2,%3};\n"
        : "+f"(c[0]), "+f"(c[1]), "+f"(c[2]), "+f"(c[3])
        : "r"(a[0]), "r"(a[1]), "r"(a[2]), "r"(a[3]), "r"(b[0]), "r"(b[1]));
}

// ---------------------------------------------------------------------------
// LayerNorm (optionally in+add, optionally store the pre-LN sum)
// ---------------------------------------------------------------------------
__global__ void k_ln(const float* __restrict__ in, const float* __restrict__ add,
                     const float* __restrict__ g, const float* __restrict__ b,
                     float* __restrict__ out, float* __restrict__ sum_out, int n)
{
    int row  = blockIdx.x * 8 + (threadIdx.x >> 5);
    int lane = threadIdx.x & 31;
    if (row >= n) return;

    float4 v = ((const float4*)in)[(size_t)row * 32 + lane];
    if (add) {
        float4 w = ((const float4*)add)[(size_t)row * 32 + lane];
        v.x += w.x; v.y += w.y; v.z += w.z; v.w += w.w;
    }
    if (sum_out) ((float4*)sum_out)[(size_t)row * 32 + lane] = v;

    float s = v.x + v.y + v.z + v.w;
    #pragma unroll
    for (int o = 16; o; o >>= 1) s += __shfl_xor_sync(0xffffffffu, s, o);
    float mu = s * (1.0f / 128.0f);

    float dx = v.x - mu, dy = v.y - mu, dz = v.z - mu, dw = v.w - mu;
    float vs = dx * dx + dy * dy + dz * dz + dw * dw;
    #pragma unroll
    for (int o = 16; o; o >>= 1) vs += __shfl_xor_sync(0xffffffffu, vs, o);
    float rs = rsqrtf(vs * (1.0f / 128.0f) + LNEPS);

    float4 gg = ((const float4*)g)[lane];
    float4 bb = ((const float4*)b)[lane];
    float4 o4;
    o4.x = dx * rs * gg.x + bb.x;
    o4.y = dy * rs * gg.y + bb.y;
    o4.z = dz * rs * gg.z + bb.z;
    o4.w = dw * rs * gg.w + bb.w;
    ((float4*)out)[(size_t)row * 32 + lane] = o4;
}

// ---------------------------------------------------------------------------
// Projection GEMM: R10-proven bf16x3 (m16n8k16), A+B fp32 split in-kernel.
// Block 128x128, BK=32, double-buffered, 8 warps (4x2), 2 CTAs/SM.
// ---------------------------------------------------------------------------
#define BK      32
#define A_STR2  20
#define B_STR2  136
#define STG_U32 (2*128*A_STR2 + 2*(BK/2)*B_STR2)
#define GEMM_SMEM_BYTES (2*STG_U32*4)

__global__ void __launch_bounds__(256, 2)
k_gemm_tc(const float* __restrict__ A,
          const float* __restrict__ B0, const float* __restrict__ B1,
          const float* __restrict__ B2,
          float* __restrict__ C, float* __restrict__ C2,
          int M, int K, int bNc, int cNc)
{
    extern __shared__ uint32_t smu[];

    int tid  = threadIdx.x;
    int warp = tid >> 5;
    int lane = tid & 31;
    int g    = lane >> 2;
    int tq   = lane & 3;
    int wr   = (warp >> 1) * 32;
    int wc   = (warp & 1) * 64;

    int row0 = blockIdx.y * 128;
    int c0   = blockIdx.x * 128;
    int bi   = c0 / bNc;
    const float* B = (bi == 0) ? B0 : ((bi == 1) ? B1 : B2);
    int bc0  = c0 - bi * bNc;

    int ar = tid >> 3;
    int ak = (tid & 7) << 2;

    float acc[2][8][4] = {};
    float4 pa[4];
    float4 pb0[2], pb1[2];

    int nch = K >> 5;

    #pragma unroll
    for (int s = 0; s < 4; ++s) {
        int node = row0 + ar + s * 32;
        pa[s] = (node < M) ? *(const float4*)&A[(size_t)node * K + ak]
                           : make_float4(0.f, 0.f, 0.f, 0.f);
    }
    #pragma unroll
    for (int s = 0; s < 2; ++s) {
        int slot = tid + s * 256;
        int kp = slot >> 5;
        int cc = (slot & 31) << 2;
        pb0[s] = *(const float4*)&B[(size_t)(2 * kp)     * bNc + bc0 + cc];
        pb1[s] = *(const float4*)&B[(size_t)(2 * kp + 1) * bNc + bc0 + cc];
    }
    {
        uint32_t* AsHi = smu;
        uint32_t* AsLo = AsHi + 128 * A_STR2;
        uint32_t* BsHi = AsLo + 128 * A_STR2;
        uint32_t* BsLo = BsHi + (BK/2) * B_STR2;
        #pragma unroll
        for (int s = 0; s < 4; ++s) {
            int r = ar + s * 32;
            uint32_t h0, l0, h1, l1;
            bfsplit(pa[s].x, pa[s].y, h0, l0);
            bfsplit(pa[s].z, pa[s].w, h1, l1);
            *(uint2*)&AsHi[r * A_STR2 + (ak >> 1)] = make_uint2(h0, h1);
            *(uint2*)&AsLo[r * A_STR2 + (ak >> 1)] = make_uint2(l0, l1);
        }
        #pragma unroll
        for (int s = 0; s < 2; ++s) {
            int slot = tid + s * 256;
            int kp = slot >> 5;
            int cc = (slot & 31) << 2;
            uint32_t h[4], l[4];
            bfsplit(pb0[s].x, pb1[s].x, h[0], l[0]);
            bfsplit(pb0[s].y, pb1[s].y, h[1], l[1]);
            bfsplit(pb0[s].z, pb1[s].z, h[2], l[2]);
            bfsplit(pb0[s].w, pb1[s].w, h[3], l[3]);
            *(uint4*)&BsHi[kp * B_STR2 + cc] = make_uint4(h[0], h[1], h[2], h[3]);
            *(uint4*)&BsLo[kp * B_STR2 + cc] = make_uint4(l[0], l[1], l[2], l[3]);
        }
    }
    __syncthreads();

    for (int ch = 0; ch < nch; ++ch) {
        int cur = ch & 1;
        uint32_t* AsHi = smu + cur * STG_U32;
        uint32_t* AsLo = AsHi + 128 * A_STR2;
        uint32_t* BsHi = AsLo + 128 * A_STR2;
        uint32_t* BsLo = BsHi + (BK/2) * B_STR2;

        bool more = (ch + 1) < nch;
        if (more) {
            int k0 = (ch + 1) << 5;
            #pragma unroll
            for (int s = 0; s < 4; ++s) {
                int node = row0 + ar + s * 32;
                pa[s] = (node < M) ? *(const float4*)&A[(size_t)node * K + k0 + ak]
                                   : make_float4(0.f, 0.f, 0.f, 0.f);
            }
            #pragma unroll
            for (int s = 0; s < 2; ++s) {
                int slot = tid + s * 256;
                int kp = slot >> 5;
                int cc = (slot & 31) << 2;
                pb0[s] = *(const float4*)&B[(size_t)(k0 + 2 * kp)     * bNc + bc0 + cc];
                pb1[s] = *(const float4*)&B[(size_t)(k0 + 2 * kp + 1) * bNc + bc0 + cc];
            }
        }

        #pragma unroll
        for (int ks = 0; ks < 2; ++ks) {
            int kb = ks * 8;
            uint32_t ahi[2][4], alo[2][4];
            #pragma unroll
            for (int mf = 0; mf < 2; ++mf) {
                int r = wr + mf * 16 + g;
                ahi[mf][0] = AsHi[r * A_STR2 + kb + tq];
                ahi[mf][1] = AsHi[(r + 8) * A_STR2 + kb + tq];
                ahi[mf][2] = AsHi[r * A_STR2 + kb + tq + 4];
                ahi[mf][3] = AsHi[(r + 8) * A_STR2 + kb + tq + 4];
                alo[mf][0] = AsLo[r * A_STR2 + kb + tq];
                alo[mf][1] = AsLo[(r + 8) * A_STR2 + kb + tq];
                alo[mf][2] = AsLo[r * A_STR2 + kb + tq + 4];
                alo[mf][3] = AsLo[(r + 8) * A_STR2 + kb + tq + 4];
            }
            #pragma unroll
            for (int nf = 0; nf < 8; ++nf) {
                int c = wc + nf * 8 + g;
                uint32_t bhi[2], blo[2];
                bhi[0] = BsHi[(kb + tq) * B_STR2 + c];
                bhi[1] = BsHi[(kb + tq + 4) * B_STR2 + c];
                blo[0] = BsLo[(kb + tq) * B_STR2 + c];
                blo[1] = BsLo[(kb + tq + 4) * B_STR2 + c];
                #pragma unroll
                for (int mf = 0; mf < 2; ++mf) {
                    mma16(acc[mf][nf], ahi[mf], bhi);
                    mma16(acc[mf][nf], ahi[mf], blo);
                    mma16(acc[mf][nf], alo[mf], bhi);
                }
            }
        }

        if (more) {
            uint32_t* nAsHi = smu + (cur ^ 1) * STG_U32;
            uint32_t* nAsLo = nAsHi + 128 * A_STR2;
            uint32_t* nBsHi = nAsLo + 128 * A_STR2;
            uint32_t* nBsLo = nBsHi + (BK/2) * B_STR2;
            #pragma unroll
            for (int s = 0; s < 4; ++s) {
                int r = ar + s * 32;
                uint32_t h0, l0, h1, l1;
                bfsplit(pa[s].x, pa[s].y, h0, l0);
                bfsplit(pa[s].z, pa[s].w, h1, l1);
                *(uint2*)&nAsHi[r * A_STR2 + (ak >> 1)] = make_uint2(h0, h1);
                *(uint2*)&nAsLo[r * A_STR2 + (ak >> 1)] = make_uint2(l0, l1);
            }
            #pragma unroll
            for (int s = 0; s < 2; ++s) {
                int slot = tid + s * 256;
                int kp = slot >> 5;
                int cc = (slot & 31) << 2;
                uint32_t h[4], l[4];
                bfsplit(pb0[s].x, pb1[s].x, h[0], l[0]);
                bfsplit(pb0[s].y, pb1[s].y, h[1], l[1]);
                bfsplit(pb0[s].z, pb1[s].z, h[2], l[2]);
                bfsplit(pb0[s].w, pb1[s].w, h[3], l[3]);
                *(uint4*)&nBsHi[kp * B_STR2 + cc] = make_uint4(h[0], h[1], h[2], h[3]);
                *(uint4*)&nBsLo[kp * B_STR2 + cc] = make_uint4(l[0], l[1], l[2], l[3]);
            }
            __syncthreads();
        }
    }

    float* Co = C;
    int ostr  = cNc;
    int ocol0 = c0;
    if (C2 && bi == 2) { Co = C2; ostr = 128; ocol0 = bc0; }

    #pragma unroll
    for (int mf = 0; mf < 2; ++mf) {
        #pragma unroll
        for (int nf = 0; nf < 8; ++nf) {
            int col = ocol0 + wc + nf * 8 + 2 * tq;
            #pragma unroll
            for (int half = 0; half < 2; ++half) {
                int row = row0 + wr + mf * 16 + g + half * 8;
                if (row >= M) continue;
                float2 r;
                r.x = acc[mf][nf][half * 2 + 0];
                r.y = acc[mf][nf][half * 2 + 1];
                *(float2*)&Co[(size_t)row * ostr + col] = r;
            }
        }
    }
}

// ---------------------------------------------------------------------------
// Fused FFN (R14/R16 form): 512 threads (16 warps, 4x4), warp tile 32x32.
// out = relu(y @ W1 + b1) @ W2 + b2 + rst; hidden never hits DRAM.
// ---------------------------------------------------------------------------
#define YA_STR 68
#define WB_STR 136
#define Y_PL   (128 * YA_STR)
#define W_PL   (64 * WB_STR)
#define FFN_SMEM_BYTES ((2*Y_PL + 2*W_PL + 2*Y_PL) * 4)

__device__ __forceinline__ void ffn_mma_block(const uint32_t* AH, const uint32_t* AL,
                                              const uint32_t* BH, const uint32_t* BL,
                                              float acc[2][4][4],
                                              int wr, int wc, int g, int tq)
{
    #pragma unroll
    for (int ks = 0; ks < 8; ++ks) {
        int kb = ks * 8;
        uint32_t ahi[2][4], alo[2][4];
        #pragma unroll
        for (int mf = 0; mf < 2; ++mf) {
            int r = wr + mf * 16 + g;
            ahi[mf][0] = AH[r * YA_STR + kb + tq];
            ahi[mf][1] = AH[(r + 8) * YA_STR + kb + tq];
            ahi[mf][2] = AH[r * YA_STR + kb + tq + 4];
            ahi[mf][3] = AH[(r + 8) * YA_STR + kb + tq + 4];
            alo[mf][0] = AL[r * YA_STR + kb + tq];
            alo[mf][1] = AL[(r + 8) * YA_STR + kb + tq];
            alo[mf][2] = AL[r * YA_STR + kb + tq + 4];
            alo[mf][3] = AL[(r + 8) * YA_STR + kb + tq + 4];
        }
        #pragma unroll
        for (int nf = 0; nf < 4; ++nf) {
            int c = wc + nf * 8 + g;
            uint32_t bhi[2], blo[2];
            bhi[0] = BH[(kb + tq) * WB_STR + c];
            bhi[1] = BH[(kb + tq + 4) * WB_STR + c];
            blo[0] = BL[(kb + tq) * WB_STR + c];
            blo[1] = BL[(kb + tq + 4) * WB_STR + c];
            #pragma unroll
            for (int mf = 0; mf < 2; ++mf) {
                mma16(acc[mf][nf], ahi[mf], bhi);
                mma16(acc[mf][nf], ahi[mf], blo);
                mma16(acc[mf][nf], alo[mf], bhi);
            }
        }
    }
}

__device__ __forceinline__ void ffn_load_w(const float* __restrict__ W, int ldw,
                                           int row_off, int col_off,
                                           uint32_t* BH, uint32_t* BL, int tid)
{
    #pragma unroll
    for (int s = 0; s < 4; ++s) {
        int slot = tid + s * 512;
        int kp = slot >> 5;
        int c4 = (slot & 31) << 2;
        float4 a = *(const float4*)&W[(size_t)(row_off + 2 * kp)     * ldw + col_off + c4];
        float4 b = *(const float4*)&W[(size_t)(row_off + 2 * kp + 1) * ldw + col_off + c4];
        uint32_t h[4], l[4];
        bfsplit(a.x, b.x, h[0], l[0]);
        bfsplit(a.y, b.y, h[1], l[1]);
        bfsplit(a.z, b.z, h[2], l[2]);
        bfsplit(a.w, b.w, h[3], l[3]);
        *(uint4*)&BH[kp * WB_STR + c4] = make_uint4(h[0], h[1], h[2], h[3]);
        *(uint4*)&BL[kp * WB_STR + c4] = make_uint4(l[0], l[1], l[2], l[3]);
    }
}

__global__ void __launch_bounds__(512, 1)
k_ffn(const float* __restrict__ Yg, const float* __restrict__ W1,
      const float* __restrict__ b1, const float* __restrict__ W2,
      const float* __restrict__ b2, const float* __restrict__ rst,
      float* __restrict__ out, int M)
{
    extern __shared__ uint32_t smu[];
    uint32_t* YH = smu;
    uint32_t* YL = YH + Y_PL;
    uint32_t* WH = YL + Y_PL;
    uint32_t* WL = WH + W_PL;
    uint32_t* HH2 = WL + W_PL;
    uint32_t* HL2 = HH2 + Y_PL;

    int tid  = threadIdx.x;
    int warp = tid >> 5;
    int lane = tid & 31;
    int g    = lane >> 2;
    int tq   = lane & 3;
    int wr   = (warp >> 2) * 32;
    int wc   = (warp & 3) * 32;
    int row0 = blockIdx.x * 128;

    #pragma unroll
    for (int s = 0; s < 4; ++s) {
        int slot = tid + s * 512;
        int r = slot >> 4;
        int i = slot & 15;
        int node = row0 + r;
        float4 v  = make_float4(0.f, 0.f, 0.f, 0.f);
        float4 v2 = make_float4(0.f, 0.f, 0.f, 0.f);
        if (node < M) {
            v  = *(const float4*)&Yg[(size_t)node * DIMC + i * 8];
            v2 = *(const float4*)&Yg[(size_t)node * DIMC + i * 8 + 4];
        }
        uint32_t h0, l0, h1, l1, h2, l2, h3, l3;
        bfsplit(v.x,  v.y,  h0, l0);
        bfsplit(v.z,  v.w,  h1, l1);
        bfsplit(v2.x, v2.y, h2, l2);
        bfsplit(v2.z, v2.w, h3, l3);
        *(uint4*)&YH[r * YA_STR + i * 4] = make_uint4(h0, h1, h2, h3);
        *(uint4*)&YL[r * YA_STR + i * 4] = make_uint4(l0, l1, l2, l3);
    }

    float accO[2][4][4] = {};

    #pragma unroll 1
    for (int cc = 0; cc < 4; ++cc) {
        int hc0 = cc * 128;

        ffn_load_w(W1, 512, 0, hc0, WH, WL, tid);
        __syncthreads();

        float accH[2][4][4] = {};
        ffn_mma_block(YH, YL, WH, WL, accH, wr, wc, g, tq);
        __syncthreads();

        #pragma unroll
        for (int mf = 0; mf < 2; ++mf) {
            #pragma unroll
            for (int nf = 0; nf < 4; ++nf) {
                int col = wc + nf * 8 + 2 * tq;
                float bx = b1[hc0 + col];
                float by = b1[hc0 + col + 1];
                #pragma unroll
                for (int half = 0; half < 2; ++half) {
                    int row = wr + mf * 16 + g + half * 8;
                    float rx = fmaxf(accH[mf][nf][half * 2 + 0] + bx, 0.f);
                    float ry = fmaxf(accH[mf][nf][half * 2 + 1] + by, 0.f);
                    uint32_t hh, ll;
                    bfsplit(rx, ry, hh, ll);
                    HH2[row * YA_STR + (col >> 1)] = hh;
                    HL2[row * YA_STR + (col >> 1)] = ll;
                }
            }
        }

        ffn_load_w(W2, 128, hc0, 0, WH, WL, tid);
        __syncthreads();

        ffn_mma_block(HH2, HL2, WH, WL, accO, wr, wc, g, tq);
        __syncthreads();
    }

    #pragma unroll
    for (int mf = 0; mf < 2; ++mf) {
        #pragma unroll
        for (int nf = 0; nf < 4; ++nf) {
            int col = wc + nf * 8 + 2 * tq;
            float bx = b2[col];
            float by = b2[col + 1];
            #pragma unroll
            for (int half = 0; half < 2; ++half) {
                int row = row0 + wr + mf * 16 + g + half * 8;
                if (row >= M) continue;
                size_t base = (size_t)row * DIMC + col;
                float2 av = *(const float2*)&rst[base];
                float2 r;
                r.x = accO[mf][nf][half * 2 + 0] + bx + av.x;
                r.y = accO[mf][nf][half * 2 + 1] + by + av.y;
                *(float2*)&out[base] = r;
            }
        }
    }
}

// ---------------------------------------------------------------------------
// Attention v3 (R10): one WARP per node. Leaky via fmax (bit-identical).
// Emits SoA lists wl[16] fp32 / sl[16] u16 per (node, head) + cnt.
// ---------------------------------------------------------------------------
#define FST 256

__global__ void k_attn(const float* __restrict__ fht, const float* __restrict__ attn,
                       const int* __restrict__ src,
                       float* __restrict__ wl, unsigned short* __restrict__ sl,
                       int* __restrict__ cnt, int n)
{
    int node = blockIdx.x * 8 + (threadIdx.x >> 5);
    if (node >= n) return;
    int lane = threadIdx.x & 31;
    int h = lane >> 2;
    int q = lane & 3;
    int fo = h * HDD + q * 4;

    int myv = 0;
    if (lane < DD) myv = src[(size_t)node * DD + lane];

    float4 ftv = *(const float4*)&fht[(size_t)node * FST + 128 + fo];
    float4 atv = *(const float4*)&attn[fo];

    float a[4];
    #pragma unroll
    for (int d = 0; d < DD; ++d) {
        int sd = __shfl_sync(0xffffffffu, myv, d);
        float4 fv = *(const float4*)&fht[(size_t)sd * FST + fo];
        float e, p = 0.f;
        e = fv.x + ftv.x; p += fmaxf(e, SLOPEC * e) * atv.x;
        e = fv.y + ftv.y; p += fmaxf(e, SLOPEC * e) * atv.y;
        e = fv.z + ftv.z; p += fmaxf(e, SLOPEC * e) * atv.z;
        e = fv.w + ftv.w; p += fmaxf(e, SLOPEC * e) * atv.w;
        p += __shfl_xor_sync(0xffffffffu, p, 1);
        p += __shfl_xor_sync(0xffffffffu, p, 2);
        if ((d >> 2) == q) a[d & 3] = p * SCORE_SCALE;
    }

    float m = fmaxf(fmaxf(a[0], a[1]), fmaxf(a[2], a[3]));
    m = fmaxf(m, __shfl_xor_sync(0xffffffffu, m, 1));
    m = fmaxf(m, __shfl_xor_sync(0xffffffffu, m, 2));
    float an[4];
    float ls = 0.f;
    #pragma unroll
    for (int j = 0; j < 4; ++j) { an[j] = expf(a[j] - m); ls += an[j]; }
    ls += __shfl_xor_sync(0xffffffffu, ls, 1);
    ls += __shfl_xor_sync(0xffffffffu, ls, 2);
    float inv = 1.f / ls;
    #pragma unroll
    for (int j = 0; j < 4; ++j) an[j] *= inv;

    unsigned alive = 0xFu;
    float thr = 0.f;
    #pragma unroll
    for (int it = 0; it < 5; ++it) {
        float lm = -1.f;
        #pragma unroll
        for (int j = 0; j < 4; ++j)
            if (alive & (1u << j)) lm = fmaxf(lm, an[j]);
        float gm = lm;
        gm = fmaxf(gm, __shfl_xor_sync(0xffffffffu, gm, 1));
        gm = fmaxf(gm, __shfl_xor_sync(0xffffffffu, gm, 2));
        thr = gm;
        int ld = 64;
        #pragma unroll
        for (int j = 3; j >= 0; --j)
            if ((alive & (1u << j)) && an[j] == gm) ld = q * 4 + j;
        int gd = ld;
        gd = min(gd, __shfl_xor_sync(0xffffffffu, gd, 1));
        gd = min(gd, __shfl_xor_sync(0xffffffffu, gd, 2));
        int loc = gd - q * 4;
        if (loc >= 0 && loc < 4) alive &= ~(1u << loc);
    }

    bool k[4];
    float ts = 0.f;
    int lcnt = 0;
    #pragma unroll
    for (int j = 0; j < 4; ++j) {
        k[j] = (an[j] >= thr);
        if (k[j]) { ts += an[j]; ++lcnt; }
    }
    ts += __shfl_xor_sync(0xffffffffu, ts, 1);
    ts += __shfl_xor_sync(0xffffffffu, ts, 2);
    float itn = 1.f / ts;

    int x = lcnt;
    int t1 = __shfl_up_sync(0xffffffffu, x, 1, 4);
    if (q >= 1) x += t1;
    int t2 = __shfl_up_sync(0xffffffffu, x, 2, 4);
    if (q >= 2) x += t2;
    int off = x - lcnt;
    int tot = __shfl_sync(0xffffffffu, x, 3, 4);

    int sj[4];
    #pragma unroll
    for (int j = 0; j < 4; ++j)
        sj[j] = __shfl_sync(0xffffffffu, myv, q * 4 + j);

    size_t base = ((size_t)node * HH + h) * 16;
    int pos = off;
    #pragma unroll
    for (int j = 0; j < 4; ++j) {
        if (k[j]) {
            wl[base + pos] = an[j] * itn;
            sl[base + pos] = (unsigned short)sj[j];
            ++pos;
        }
    }
    if (q == 0) cnt[(size_t)node * HH + h] = tot;
}

// ---------------------------------------------------------------------------
// Shared hop body (R10): predicated 8-way gathers + rare tail.
// ---------------------------------------------------------------------------
__device__ __forceinline__ float4 hop_acc(const float* __restrict__ hin,
                                          const float* __restrict__ wl,
                                          const unsigned short* __restrict__ sl,
                                          int c, size_t lb, int fo)
{
    float4 w0 = *(const float4*)&wl[lb];
    float4 w1 = *(const float4*)&wl[lb + 4];
    uint4  sp = *(const uint4*)&sl[lb];
    const unsigned short* sjp = (const unsigned short*)&sp;
    float wj[8] = {w0.x, w0.y, w0.z, w0.w, w1.x, w1.y, w1.z, w1.w};

    float4 acc = {0.f, 0.f, 0.f, 0.f};
    #pragma unroll
    for (int j = 0; j < 8; ++j) {
        if (j < c) {
            float4 v = *(const float4*)&hin[(size_t)sjp[j] * DIMC + fo];
            acc.x += wj[j] * v.x; acc.y += wj[j] * v.y;
            acc.z += wj[j] * v.z; acc.w += wj[j] * v.w;
        }
    }
    for (int j = 8; j < c; ++j) {
        float w = wl[lb + j];
        int   s = sl[lb + j];
        float4 v = *(const float4*)&hin[(size_t)s * DIMC + fo];
        acc.x += w * v.x; acc.y += w * v.y; acc.z += w * v.z; acc.w += w * v.w;
    }
    return acc;
}

// ---------------------------------------------------------------------------
// One propagation hop. One warp per node. fe read with streaming hint so the
// gather-heavy hin/hout/lists stay L2-resident.
// ---------------------------------------------------------------------------
__global__ void k_hop(const float* __restrict__ hin, const float* __restrict__ fe,
                      const float* __restrict__ wl, const unsigned short* __restrict__ sl,
                      const int* __restrict__ cnt, float* __restrict__ hout, int n)
{
    int node = blockIdx.x * 8 + (threadIdx.x >> 5);
    if (node >= n) return;
    int lane = threadIdx.x & 31;
    int h = lane >> 2;
    int q = lane & 3;
    int fo = h * HDD + q * 4;

    size_t lb = ((size_t)node * HH + h) * 16;
    int c = cnt[(size_t)node * HH + h];

    float4 acc = hop_acc(hin, wl, sl, c, lb, fo);

    size_t o = (size_t)node * DIMC + fo;
    float4 f = __ldcs((const float4*)&fe[o]);
    float4 r;
    r.x = (1.f - ALPHAC) * acc.x + ALPHAC * f.x;
    r.y = (1.f - ALPHAC) * acc.y + ALPHAC * f.y;
    r.z = (1.f - ALPHAC) * acc.z + ALPHAC * f.z;
    r.w = (1.f - ALPHAC) * acc.w + ALPHAC * f.w;
    *(float4*)&hout[o] = r;
}

// ---------------------------------------------------------------------------
// Final hop fused with residual add + LayerNorm2.
// ---------------------------------------------------------------------------
__global__ void k_hoplast(const float* __restrict__ hin, const float* __restrict__ fe,
                          const float* __restrict__ feat,
                          const float* __restrict__ g, const float* __restrict__ b,
                          const float* __restrict__ wl, const unsigned short* __restrict__ sl,
                          const int* __restrict__ cnt,
                          float* __restrict__ y, float* __restrict__ rst, int n)
{
    int node = blockIdx.x * 8 + (threadIdx.x >> 5);
    if (node >= n) return;
    int lane = threadIdx.x & 31;
    int h = lane >> 2;
    int q = lane & 3;
    int fo = h * HDD + q * 4;

    size_t lb = ((size_t)node * HH + h) * 16;
    int c = cnt[(size_t)node * HH + h];

    float4 acc = hop_acc(hin, wl, sl, c, lb, fo);

    size_t o = (size_t)node * DIMC + fo;
    float4 f  = __ldcs((const float4*)&fe[o]);
    float4 ft = __ldcs((const float4*)&feat[o]);
    float4 v;
    v.x = (1.f - ALPHAC) * acc.x + ALPHAC * f.x + ft.x;
    v.y = (1.f - ALPHAC) * acc.y + ALPHAC * f.y + ft.y;
    v.z = (1.f - ALPHAC) * acc.z + ALPHAC * f.z + ft.z;
    v.w = (1.f - ALPHAC) * acc.w + ALPHAC * f.w + ft.w;
    *(float4*)&rst[o] = v;

    float s = v.x + v.y + v.z + v.w;
    #pragma unroll
    for (int off = 16; off; off >>= 1) s += __shfl_xor_sync(0xffffffffu, s, off);
    float mu = s * (1.0f / 128.0f);

    float dx = v.x - mu, dy = v.y - mu, dz = v.z - mu, dw = v.w - mu;
    float vs = dx * dx + dy * dy + dz * dz + dw * dw;
    #pragma unroll
    for (int off = 16; off; off >>= 1) vs += __shfl_xor_sync(0xffffffffu, vs, off);
    float rs = rsqrtf(vs * (1.0f / 128.0f) + LNEPS);

    float4 gg = *(const float4*)&g[fo];
    float4 bb = *(const float4*)&b[fo];
    float4 o4;
    o4.x = dx * rs * gg.x + bb.x;
    o4.y = dy * rs * gg.y + bb.y;
    o4.z = dz * rs * gg.z + bb.z;
    o4.w = dw * rs * gg.w + bb.w;
    *(float4*)&y[o] = o4;
}

// ---------------------------------------------------------------------------
extern "C" void kernel_launch(void* const* d_in, const int* in_sizes, int n_in,
                              void* d_out, int out_size)
{
    const float* feat   = (const float*)d_in[0];
    const float* W_head = (const float*)d_in[1];
    const float* W_tail = (const float*)d_in[2];
    const float* W_ent  = (const float*)d_in[3];
    const float* attn   = (const float*)d_in[4];
    const float* g1     = (const float*)d_in[5];
    const float* b1     = (const float*)d_in[6];
    const float* g2     = (const float*)d_in[7];
    const float* b2     = (const float*)d_in[8];
    const float* W_ff1  = (const float*)d_in[9];
    const float* b_ff1  = (const float*)d_in[10];
    const float* W_ff2  = (const float*)d_in[11];
    const float* b_ff2  = (const float*)d_in[12];
    const int*   src    = (const int*)d_in[13];
    float* out = (float*)d_out;

    int n = in_sizes[0] / DIMC;   // 50000
    if (n > NNODES) n = NNODES;

    float* scratch = nullptr;
    cudaGetSymbolAddress((void**)&scratch, g_scratch);
    const size_t SZ = (size_t)NNODES * DIMC;
    float* xln    = scratch + 0 * SZ;
    float* fht    = scratch + 1 * SZ;          // N*256: fh|ft packed
    float* fe     = scratch + 3 * SZ;          // N*128 dense
    float* h0     = scratch + 4 * SZ;
    float* h1     = scratch + 5 * SZ;
    float* rst    = scratch + 6 * SZ;
    float* y      = scratch + 7 * SZ;
    float* wlist  = scratch + 8 * SZ;          // N*8*16 floats
    unsigned short* slist = (unsigned short*)(scratch + 9 * SZ); // N*8*16 u16
    int*   cnt    = (int*)(scratch + 10 * SZ); // N*8

    cudaFuncSetAttribute(k_gemm_tc, cudaFuncAttributeMaxDynamicSharedMemorySize,
                         GEMM_SMEM_BYTES);
    cudaFuncSetAttribute(k_ffn, cudaFuncAttributeMaxDynamicSharedMemorySize,
                         FFN_SMEM_BYTES);

    int lnGrid  = (n + 7) / 8;
    int mTiles  = (n + 127) / 128;
    int w8Grid  = (n + 7) / 8;

    // 1) x = LN(feat)
    k_ln<<<lnGrid, 256>>>(feat, nullptr, g1, b1, xln, nullptr, n);

    // 2) fused projection: tiles 0,1 -> fht [N,256]; tile 2 -> fe dense
    dim3 gp(3, mTiles);
    k_gemm_tc<<<gp, 256, GEMM_SMEM_BYTES>>>(xln, W_head, W_tail, W_ent,
                                            fht, fe, n, 128, 128, 256);

    // 3) attention -> compact top-k SoA lists
    k_attn<<<w8Grid, 256>>>(fht, attn, src, wlist, slist, cnt, n);

    // 4) 4 plain hops + final fused hop (hop5 + residual + LN2)
    k_hop<<<w8Grid, 256>>>(fe, fe, wlist, slist, cnt, h0, n);
    k_hop<<<w8Grid, 256>>>(h0, fe, wlist, slist, cnt, h1, n);
    k_hop<<<w8Grid, 256>>>(h1, fe, wlist, slist, cnt, h0, n);
    k_hop<<<w8Grid, 256>>>(h0, fe, wlist, slist, cnt, h1, n);
    k_hoplast<<<w8Grid, 256>>>(h1, fe, feat, g2, b2, wlist, slist, cnt, y, rst, n);

    // 5) fused FFN: out = relu(y@W1+b1)@W2 + b2 + rst
    k_ffn<<<mTiles, 512, FFN_SMEM_BYTES>>>(y, W_ff1, b_ff1, W_ff2, b_ff2,
                                           rst, out, n);
}